// round 12
// baseline (speedup 1.0000x reference)
#include <cuda_runtime.h>
#include <cstdint>

#define NP 200000
#define NA 100000
#define NI 8000
#define NF 30000
#define HD 256
#define NOUT 349
#define E_C 500000
#define E_W 400000
#define E_A 100000
#define E_T 300000

// ---------------- scratch (static device allocations, allowed) ----------------
__device__ float g_mp0[(size_t)NP * HD];   // m0: mean cites(p) raw
__device__ float g_mp1[(size_t)NP * HD];   // g1: mean writes(a@Wl1)
__device__ float g_mp6[(size_t)NP * HD];   // g6: mean rev_topic(f@Wl6)
__device__ float g_ma2[(size_t)NA * HD];   // ma2: mean rev_writes(p) raw
__device__ float g_ma4[(size_t)NA * HD];   // g4: mean rev_aff(i@Wl4)
__device__ float g_mi3[(size_t)NI * HD];   // mi3: mean aff(a) raw
__device__ float g_mf5[(size_t)NF * HD];   // mf5: mean topic(p) raw

__device__ float g_tA[(size_t)NA * HD];    // a @ Wl1
__device__ float g_tI[(size_t)NI * HD];    // i @ Wl4
__device__ float g_tF[(size_t)NF * HD];    // f @ Wl6

__device__ float g_pb[2][(size_t)NP * HD]; // ping-pong node features
__device__ float g_ab[2][(size_t)NA * HD];
__device__ float g_ib[2][(size_t)NI * HD];
__device__ float g_fb[2][(size_t)NF * HD];

__device__ float g_WrP[2 * HD * HD];       // combined Wr for paper (r0+r1+r6), per layer
__device__ float g_WrA[2 * HD * HD];       // combined Wr for author (r2+r4)
__device__ float g_bP[2 * HD];
__device__ float g_bA[2 * HD];

// CSR scratch: cnt doubles as cursor after scan
__device__ int g_cnt_c[NP];   __device__ int g_off_c[NP + 1];   __device__ int g_adj_c[E_C];
__device__ int g_cnt_w[NP];   __device__ int g_off_w[NP + 1];   __device__ int g_adj_w[E_W];
__device__ int g_cnt_rw[NA];  __device__ int g_off_rw[NA + 1];  __device__ int g_adj_rw[E_W];
__device__ int g_cnt_af[NI];  __device__ int g_off_af[NI + 1];  __device__ int g_adj_af[E_A];
__device__ int g_cnt_raf[NA]; __device__ int g_off_raf[NA + 1]; __device__ int g_adj_raf[E_A];
__device__ int g_cnt_t[NF];   __device__ int g_off_t[NF + 1];   __device__ int g_adj_t[E_T];
__device__ int g_cnt_rt[NP];  __device__ int g_off_rt[NP + 1];  __device__ int g_adj_rt[E_T];

// ---------------- small kernels ----------------
__global__ void hist_kernel(const int* __restrict__ dst, int E, int* cnt) {
    int i = blockIdx.x * blockDim.x + threadIdx.x;
    if (i < E) atomicAdd(&cnt[dst[i]], 1);
}

__global__ void scan_kernel(int* cnt, int n, int* offs) {
    __shared__ int sh[1024];
    int tid = threadIdx.x;
    int chunk = (n + 1023) >> 10;
    int beg = tid * chunk;
    int end = beg + chunk; if (end > n) end = n;
    int s = 0;
    for (int i = beg; i < end; i++) s += cnt[i];
    sh[tid] = s;
    __syncthreads();
    for (int d = 1; d < 1024; d <<= 1) {
        int t = (tid >= d) ? sh[tid - d] : 0;
        __syncthreads();
        sh[tid] += t;
        __syncthreads();
    }
    int run = sh[tid] - s;
    for (int i = beg; i < end; i++) {
        int c = cnt[i];
        offs[i] = run;
        cnt[i]  = run;
        run += c;
    }
    if (beg < n && end == n) offs[n] = run;
}

__global__ void fill_kernel(const int* __restrict__ src, const int* __restrict__ dst,
                            int E, int* cursor, int* __restrict__ adj) {
    int i = blockIdx.x * blockDim.x + threadIdx.x;
    if (i < E) {
        int p = atomicAdd(&cursor[dst[i]], 1);
        adj[p] = src[i];
    }
}

// mean aggregation: 64 threads per dst node (float4 per thread), 4 nodes per block
__global__ void gather_mean_kernel(const float* __restrict__ x,
                                   const int* __restrict__ offs,
                                   const int* __restrict__ adj,
                                   float* __restrict__ out, int n_dst) {
    int node = blockIdx.x * 4 + (threadIdx.x >> 6);
    int lane = threadIdx.x & 63;
    if (node >= n_dst) return;
    int beg = offs[node], end = offs[node + 1];
    float4 acc = make_float4(0.f, 0.f, 0.f, 0.f);
    int e = beg;
    for (; e + 1 < end; e += 2) {
        int s0 = adj[e], s1 = adj[e + 1];
        float4 v0 = ((const float4*)(x + (size_t)s0 * HD))[lane];
        float4 v1 = ((const float4*)(x + (size_t)s1 * HD))[lane];
        acc.x += v0.x + v1.x; acc.y += v0.y + v1.y;
        acc.z += v0.z + v1.z; acc.w += v0.w + v1.w;
    }
    if (e < end) {
        float4 v = ((const float4*)(x + (size_t)adj[e] * HD))[lane];
        acc.x += v.x; acc.y += v.y; acc.z += v.z; acc.w += v.w;
    }
    float inv = (end > beg) ? 1.f / (float)(end - beg) : 0.f;
    float4 r = make_float4(acc.x * inv, acc.y * inv, acc.z * inv, acc.w * inv);
    ((float4*)(out + (size_t)node * HD))[lane] = r;
}

__global__ void combine_kernel(const float* __restrict__ Wr, const float* __restrict__ bl,
                               float* __restrict__ WrP, float* __restrict__ WrA,
                               float* __restrict__ bP, float* __restrict__ bA) {
    int idx = blockIdx.x * blockDim.x + threadIdx.x;
    if (idx < 2 * HD * HD) {
        int l = idx / (HD * HD), j = idx % (HD * HD);
        const float* base = Wr + (size_t)l * 7 * HD * HD;
        WrP[idx] = base[0 * HD * HD + j] + base[1 * HD * HD + j] + base[6 * HD * HD + j];
        WrA[idx] = base[2 * HD * HD + j] + base[4 * HD * HD + j];
    }
    if (idx < 2 * HD) {
        int l = idx / HD, j = idx % HD;
        const float* bb = bl + (size_t)l * 7 * HD;
        bP[idx] = bb[0 * HD + j] + bb[1 * HD + j] + bb[6 * HD + j];
        bA[idx] = bb[2 * HD + j] + bb[4 * HD + j];
    }
}

// ---------------- tf32 tensor-core multi-part GEMM, register-staged pipeline ---
// C[M,N] = act( sum_p A_p[M,256] @ W_p[256,N] + bias + add0 + add1 )
struct GemmArgs {
    const float* A[2];
    const float* W[2];
    const float* add0; const float* add1;
    const float* bias;
    float* C;
    int nparts, nadd, M, N, relu;
};

__device__ __forceinline__ float to_tf32(float x) {
    uint32_t u;
    asm("cvt.rna.tf32.f32 %0, %1;" : "=r"(u) : "f"(x));
    return __uint_as_float(u);
}

__device__ __forceinline__ void mma_tf32(float* c, const uint32_t* a, const uint32_t* b) {
    asm volatile(
        "mma.sync.aligned.m16n8k8.row.col.f32.tf32.tf32.f32 "
        "{%0,%1,%2,%3}, {%4,%5,%6,%7}, {%8,%9}, {%0,%1,%2,%3};\n"
        : "+f"(c[0]), "+f"(c[1]), "+f"(c[2]), "+f"(c[3])
        : "r"(a[0]), "r"(a[1]), "r"(a[2]), "r"(a[3]), "r"(b[0]), "r"(b[1]));
}

#define BK 32
#define APITCH 136  // 136 % 32 == 8 -> fragment loads (bank = 8*tig + g) conflict-free

__global__ __launch_bounds__(256) void gemm_tf32_kernel(GemmArgs g) {
    __shared__ float As[2][BK][APITCH];  // k-major: As[buf][k][m]
    __shared__ float Bs[2][BK][APITCH];  // k-major: Bs[buf][k][n]

    int tid = threadIdx.x;
    int bm = blockIdx.y * 128;
    int bn = blockIdx.x * 128;
    int warp = tid >> 5, lane = tid & 31;
    int warp_m = warp >> 2;          // 0..1  -> 64 rows each
    int warp_n = warp & 3;           // 0..3  -> 32 cols each
    int gq = lane >> 2, tig = lane & 3;

    // A loader: thread covers row lm, 16 consecutive k at lk*16
    int lm = tid & 127;
    int lk = tid >> 7;               // 0/1
    bool arow_ok = (bm + lm) < g.M;

    // B loader: thread covers 4 cols at nc, k rows kr+{0,8,16,24}
    int nc = (tid & 31) * 4;
    int kr = tid >> 5;               // 0..7

    float acc[4][4][4];
#pragma unroll
    for (int i = 0; i < 4; i++)
#pragma unroll
        for (int j = 0; j < 4; j++)
#pragma unroll
            for (int q = 0; q < 4; q++) acc[i][j][q] = 0.f;

    int nchunks = g.nparts * (HD / BK);   // 8 or 16

    // register staging buffers
    float4 aReg[4];
    float  bReg[4][4];

    // ---- chunk loaders (gmem -> regs, regs -> smem[buf]) ----
    auto load_chunk = [&](int c) {
        int part = c >> 3;
        int k0 = (c & 7) * BK;
        const float* A = g.A[part];
        const float* W = g.W[part];
        const float* Arow = A + (size_t)(bm + lm) * HD + k0 + lk * 16;
#pragma unroll
        for (int i = 0; i < 4; i++) {
            aReg[i] = arow_ok ? *(const float4*)(Arow + i * 4)
                              : make_float4(0.f, 0.f, 0.f, 0.f);
        }
#pragma unroll
        for (int i = 0; i < 4; i++) {
            const float* Wp = W + (size_t)(k0 + kr + i * 8) * g.N + bn + nc;
#pragma unroll
            for (int j = 0; j < 4; j++)
                bReg[i][j] = (bn + nc + j < g.N) ? Wp[j] : 0.f;
        }
    };
    auto store_chunk = [&](int buf) {
#pragma unroll
        for (int i = 0; i < 4; i++) {
            int kk = lk * 16 + i * 4;
            As[buf][kk + 0][lm] = to_tf32(aReg[i].x);
            As[buf][kk + 1][lm] = to_tf32(aReg[i].y);
            As[buf][kk + 2][lm] = to_tf32(aReg[i].z);
            As[buf][kk + 3][lm] = to_tf32(aReg[i].w);
        }
#pragma unroll
        for (int i = 0; i < 4; i++) {
            float4 v;
            v.x = to_tf32(bReg[i][0]); v.y = to_tf32(bReg[i][1]);
            v.z = to_tf32(bReg[i][2]); v.w = to_tf32(bReg[i][3]);
            *(float4*)(&Bs[buf][kr + i * 8][nc]) = v;
        }
    };

    load_chunk(0);
    store_chunk(0);
    __syncthreads();

    for (int c = 0; c < nchunks; c++) {
        int buf = c & 1;
        if (c + 1 < nchunks) load_chunk(c + 1);   // LDG overlapped with compute

        // ---- 4 k8-steps of m16n8k8 tf32 mma on smem[buf] ----
#pragma unroll
        for (int ks = 0; ks < 4; ks++) {
            int kb = ks * 8;
            uint32_t afr[4][4];
#pragma unroll
            for (int i = 0; i < 4; i++) {
                int mb = warp_m * 64 + i * 16;
                afr[i][0] = __float_as_uint(As[buf][kb + tig][mb + gq]);
                afr[i][1] = __float_as_uint(As[buf][kb + tig][mb + gq + 8]);
                afr[i][2] = __float_as_uint(As[buf][kb + tig + 4][mb + gq]);
                afr[i][3] = __float_as_uint(As[buf][kb + tig + 4][mb + gq + 8]);
            }
            uint32_t bfr[4][2];
#pragma unroll
            for (int j = 0; j < 4; j++) {
                int nb = warp_n * 32 + j * 8;
                bfr[j][0] = __float_as_uint(Bs[buf][kb + tig][nb + gq]);
                bfr[j][1] = __float_as_uint(Bs[buf][kb + tig + 4][nb + gq]);
            }
#pragma unroll
            for (int i = 0; i < 4; i++)
#pragma unroll
                for (int j = 0; j < 4; j++)
                    mma_tf32(acc[i][j], afr[i], bfr[j]);
        }

        if (c + 1 < nchunks) store_chunk(1 - buf); // writes the other buffer
        __syncthreads();                           // one barrier per chunk
    }

    // ---- epilogue: addends + bias + relu + guarded store ----
#pragma unroll
    for (int i = 0; i < 4; i++) {
        int r0 = bm + warp_m * 64 + i * 16 + gq;
        int r1 = r0 + 8;
#pragma unroll
        for (int j = 0; j < 4; j++) {
            int c0 = bn + warp_n * 32 + j * 8 + tig * 2;
            bool c0ok = c0 < g.N, c1ok = (c0 + 1) < g.N;
            float bia0 = 0.f, bia1 = 0.f;
            if (g.bias) {
                if (c0ok) bia0 = g.bias[c0];
                if (c1ok) bia1 = g.bias[c0 + 1];
            }
            float v00 = acc[i][j][0] + bia0, v01 = acc[i][j][1] + bia1;
            float v10 = acc[i][j][2] + bia0, v11 = acc[i][j][3] + bia1;
            if (g.nadd > 0) {
                const float* a0p = g.add0;
                if (r0 < g.M) {
                    if (c0ok) v00 += a0p[(size_t)r0 * g.N + c0];
                    if (c1ok) v01 += a0p[(size_t)r0 * g.N + c0 + 1];
                }
                if (r1 < g.M) {
                    if (c0ok) v10 += a0p[(size_t)r1 * g.N + c0];
                    if (c1ok) v11 += a0p[(size_t)r1 * g.N + c0 + 1];
                }
            }
            if (g.nadd > 1) {
                const float* a1p = g.add1;
                if (r0 < g.M) {
                    if (c0ok) v00 += a1p[(size_t)r0 * g.N + c0];
                    if (c1ok) v01 += a1p[(size_t)r0 * g.N + c0 + 1];
                }
                if (r1 < g.M) {
                    if (c0ok) v10 += a1p[(size_t)r1 * g.N + c0];
                    if (c1ok) v11 += a1p[(size_t)r1 * g.N + c0 + 1];
                }
            }
            if (g.relu) {
                v00 = v00 > 0.f ? v00 : 0.f; v01 = v01 > 0.f ? v01 : 0.f;
                v10 = v10 > 0.f ? v10 : 0.f; v11 = v11 > 0.f ? v11 : 0.f;
            }
            if (r0 < g.M) {
                if (c0ok) g.C[(size_t)r0 * g.N + c0]     = v00;
                if (c1ok) g.C[(size_t)r0 * g.N + c0 + 1] = v01;
            }
            if (r1 < g.M) {
                if (c0ok) g.C[(size_t)r1 * g.N + c0]     = v10;
                if (c1ok) g.C[(size_t)r1 * g.N + c0 + 1] = v11;
            }
        }
    }
}

// ---------------- host ----------------
static inline int cdiv(int a, int b) { return (a + b - 1) / b; }

static void launch_gemm(int M, int N, int nparts,
                        const float* A0, const float* W0,
                        const float* A1, const float* W1,
                        int nadd, const float* add0, const float* add1,
                        const float* bias, float* C, int relu) {
    GemmArgs g;
    g.A[0] = A0; g.A[1] = A1; g.W[0] = W0; g.W[1] = W1;
    g.add0 = add0; g.add1 = add1;
    g.nparts = nparts; g.nadd = nadd; g.M = M; g.N = N;
    g.bias = bias; g.C = C; g.relu = relu;
    dim3 grid(cdiv(N, 128), cdiv(M, 128));
    gemm_tf32_kernel<<<grid, 256>>>(g);
}

extern "C" void kernel_launch(void* const* d_in, const int* in_sizes, int n_in,
                              void* d_out, int out_size) {
    const float* xp = (const float*)d_in[0];
    const float* xa = (const float*)d_in[1];
    const float* xi = (const float*)d_in[2];
    const float* xf = (const float*)d_in[3];
    const int* cites_src = (const int*)d_in[4];
    const int* cites_dst = (const int*)d_in[5];
    const int* writes_src = (const int*)d_in[6];
    const int* writes_dst = (const int*)d_in[7];
    const int* rwrites_src = (const int*)d_in[8];
    const int* rwrites_dst = (const int*)d_in[9];
    const int* aff_src = (const int*)d_in[10];
    const int* aff_dst = (const int*)d_in[11];
    const int* raff_src = (const int*)d_in[12];
    const int* raff_dst = (const int*)d_in[13];
    const int* topic_src = (const int*)d_in[14];
    const int* topic_dst = (const int*)d_in[15];
    const int* rtopic_src = (const int*)d_in[16];
    const int* rtopic_dst = (const int*)d_in[17];
    const float* Wl = (const float*)d_in[18];
    const float* bl = (const float*)d_in[19];
    const float* Wr = (const float*)d_in[20];
    const float* Wout = (const float*)d_in[21];
    const float* bout = (const float*)d_in[22];

    float *m0, *gg1, *gg6, *ma2, *gg4, *mi3, *mf5, *tA, *tI, *tF;
    float *pb, *ab, *ib, *fb, *WrP, *WrA, *bP, *bA;
    int *cnt_c, *off_c, *adj_c, *cnt_w, *off_w, *adj_w;
    int *cnt_rw, *off_rw, *adj_rw, *cnt_af, *off_af, *adj_af;
    int *cnt_raf, *off_raf, *adj_raf, *cnt_t, *off_t, *adj_t;
    int *cnt_rt, *off_rt, *adj_rt;
    cudaGetSymbolAddress((void**)&m0, g_mp0);
    cudaGetSymbolAddress((void**)&gg1, g_mp1);
    cudaGetSymbolAddress((void**)&gg6, g_mp6);
    cudaGetSymbolAddress((void**)&ma2, g_ma2);
    cudaGetSymbolAddress((void**)&gg4, g_ma4);
    cudaGetSymbolAddress((void**)&mi3, g_mi3);
    cudaGetSymbolAddress((void**)&mf5, g_mf5);
    cudaGetSymbolAddress((void**)&tA, g_tA);
    cudaGetSymbolAddress((void**)&tI, g_tI);
    cudaGetSymbolAddress((void**)&tF, g_tF);
    cudaGetSymbolAddress((void**)&pb, g_pb);
    cudaGetSymbolAddress((void**)&ab, g_ab);
    cudaGetSymbolAddress((void**)&ib, g_ib);
    cudaGetSymbolAddress((void**)&fb, g_fb);
    cudaGetSymbolAddress((void**)&WrP, g_WrP);
    cudaGetSymbolAddress((void**)&WrA, g_WrA);
    cudaGetSymbolAddress((void**)&bP, g_bP);
    cudaGetSymbolAddress((void**)&bA, g_bA);
    cudaGetSymbolAddress((void**)&cnt_c, g_cnt_c);
    cudaGetSymbolAddress((void**)&off_c, g_off_c);
    cudaGetSymbolAddress((void**)&adj_c, g_adj_c);
    cudaGetSymbolAddress((void**)&cnt_w, g_cnt_w);
    cudaGetSymbolAddress((void**)&off_w, g_off_w);
    cudaGetSymbolAddress((void**)&adj_w, g_adj_w);
    cudaGetSymbolAddress((void**)&cnt_rw, g_cnt_rw);
    cudaGetSymbolAddress((void**)&off_rw, g_off_rw);
    cudaGetSymbolAddress((void**)&adj_rw, g_adj_rw);
    cudaGetSymbolAddress((void**)&cnt_af, g_cnt_af);
    cudaGetSymbolAddress((void**)&off_af, g_off_af);
    cudaGetSymbolAddress((void**)&adj_af, g_adj_af);
    cudaGetSymbolAddress((void**)&cnt_raf, g_cnt_raf);
    cudaGetSymbolAddress((void**)&off_raf, g_off_raf);
    cudaGetSymbolAddress((void**)&adj_raf, g_adj_raf);
    cudaGetSymbolAddress((void**)&cnt_t, g_cnt_t);
    cudaGetSymbolAddress((void**)&off_t, g_off_t);
    cudaGetSymbolAddress((void**)&adj_t, g_adj_t);
    cudaGetSymbolAddress((void**)&cnt_rt, g_cnt_rt);
    cudaGetSymbolAddress((void**)&off_rt, g_off_rt);
    cudaGetSymbolAddress((void**)&adj_rt, g_adj_rt);

    float* pbuf[2] = { pb, pb + (size_t)NP * HD };
    float* abuf[2] = { ab, ab + (size_t)NA * HD };
    float* ibuf[2] = { ib, ib + (size_t)NI * HD };
    float* fbuf[2] = { fb, fb + (size_t)NF * HD };

    // ---- build CSR for all 7 relations (reused by both layers) ----
    struct Rel { const int* src; const int* dst; int E; int n_dst; int* cnt; int* off; int* adj; };
    Rel rels[7] = {
        { cites_src,   cites_dst,   E_C, NP, cnt_c,   off_c,   adj_c   },
        { writes_src,  writes_dst,  E_W, NP, cnt_w,   off_w,   adj_w   },
        { rwrites_src, rwrites_dst, E_W, NA, cnt_rw,  off_rw,  adj_rw  },
        { aff_src,     aff_dst,     E_A, NI, cnt_af,  off_af,  adj_af  },
        { raff_src,    raff_dst,    E_A, NA, cnt_raf, off_raf, adj_raf },
        { topic_src,   topic_dst,   E_T, NF, cnt_t,   off_t,   adj_t   },
        { rtopic_src,  rtopic_dst,  E_T, NP, cnt_rt,  off_rt,  adj_rt  },
    };
    for (int r = 0; r < 7; r++) {
        cudaMemsetAsync(rels[r].cnt, 0, (size_t)rels[r].n_dst * sizeof(int), 0);
        hist_kernel<<<cdiv(rels[r].E, 256), 256>>>(rels[r].dst, rels[r].E, rels[r].cnt);
        scan_kernel<<<1, 1024>>>(rels[r].cnt, rels[r].n_dst, rels[r].off);
        fill_kernel<<<cdiv(rels[r].E, 256), 256>>>(rels[r].src, rels[r].dst, rels[r].E,
                                                   rels[r].cnt, rels[r].adj);
    }

    combine_kernel<<<cdiv(2 * HD * HD, 256), 256>>>(Wr, bl, WrP, WrA, bP, bA);

    // ---- 2 SAGE layers (smart-side: transform small side first, gather after) ----
    const float* cp = xp; const float* ca = xa; const float* ci = xi; const float* cf = xf;
    for (int l = 0; l < 2; l++) {
        const size_t WSZ = (size_t)HD * HD;
        const float* WlL = Wl + (size_t)l * 7 * WSZ;
        const float* blL = bl + (size_t)l * 7 * HD;

        // src-side transforms (linearity: mean(x)@W == mean(x@W))
        launch_gemm(NA, HD, 1, ca, WlL + 1 * WSZ, 0, 0, 0, 0, 0, 0, tA, 0);
        launch_gemm(NF, HD, 1, cf, WlL + 6 * WSZ, 0, 0, 0, 0, 0, 0, tF, 0);
        launch_gemm(NI, HD, 1, ci, WlL + 4 * WSZ, 0, 0, 0, 0, 0, 0, tI, 0);

        // gathers
        gather_mean_kernel<<<cdiv(NP, 4), 256>>>(cp, off_c,   adj_c,   m0,  NP);  // raw
        gather_mean_kernel<<<cdiv(NP, 4), 256>>>(tA, off_w,   adj_w,   gg1, NP);  // transformed
        gather_mean_kernel<<<cdiv(NP, 4), 256>>>(tF, off_rt,  adj_rt,  gg6, NP);  // transformed
        gather_mean_kernel<<<cdiv(NA, 4), 256>>>(cp, off_rw,  adj_rw,  ma2, NA);  // raw
        gather_mean_kernel<<<cdiv(NA, 4), 256>>>(tI, off_raf, adj_raf, gg4, NA);  // transformed
        gather_mean_kernel<<<cdiv(NI, 4), 256>>>(ca, off_af,  adj_af,  mi3, NI);  // raw
        gather_mean_kernel<<<cdiv(NF, 4), 256>>>(cp, off_t,   adj_t,   mf5, NF);  // raw

        // output GEMMs
        // new_p = relu(m0@Wl0 + p@WrP + bP + g1 + g6)
        launch_gemm(NP, HD, 2, m0, WlL + 0 * WSZ, cp, WrP + (size_t)l * WSZ,
                    2, gg1, gg6, bP + (size_t)l * HD, pbuf[l], 1);
        // new_a = relu(ma2@Wl2 + a@WrA + bA + g4)
        launch_gemm(NA, HD, 2, ma2, WlL + 2 * WSZ, ca, WrA + (size_t)l * WSZ,
                    1, gg4, 0, bA + (size_t)l * HD, abuf[l], 1);
        // new_i = relu(mi3@Wl3 + i@Wr3 + bl3)
        launch_gemm(NI, HD, 2, mi3, WlL + 3 * WSZ, ci, Wr + ((size_t)l * 7 + 3) * WSZ,
                    0, 0, 0, blL + 3 * HD, ibuf[l], 1);
        // new_f = relu(mf5@Wl5 + f@Wr5 + bl5)
        launch_gemm(NF, HD, 2, mf5, WlL + 5 * WSZ, cf, Wr + ((size_t)l * 7 + 5) * WSZ,
                    0, 0, 0, blL + 5 * HD, fbuf[l], 1);

        cp = pbuf[l]; ca = abuf[l]; ci = ibuf[l]; cf = fbuf[l];
    }

    // ---- final projection: out = p @ W_out + b_out ----
    launch_gemm(NP, NOUT, 1, cp, Wout, 0, 0, 0, 0, 0, bout, (float*)d_out, 0);
}

// round 13
// speedup vs baseline: 1.0605x; 1.0605x over previous
#include <cuda_runtime.h>
#include <cstdint>

#define NP 200000
#define NA 100000
#define NI 8000
#define NF 30000
#define HD 256
#define NOUT 349
#define E_C 500000
#define E_W 400000
#define E_A 100000
#define E_T 300000

// ---------------- scratch (static device allocations, allowed) ----------------
__device__ float g_mp0[(size_t)NP * HD];   // m0: mean cites(p) raw
__device__ float g_mp1[(size_t)NP * HD];   // g1: mean writes(a@Wl1)
__device__ float g_mp6[(size_t)NP * HD];   // g6: mean rev_topic(f@Wl6)
__device__ float g_ma2[(size_t)NA * HD];   // ma2: mean rev_writes(p) raw
__device__ float g_ma4[(size_t)NA * HD];   // g4: mean rev_aff(i@Wl4)
__device__ float g_mi3[(size_t)NI * HD];   // mi3: mean aff(a) raw
__device__ float g_mf5[(size_t)NF * HD];   // mf5: mean topic(p) raw

__device__ float g_tA[(size_t)NA * HD];    // a @ Wl1
__device__ float g_tI[(size_t)NI * HD];    // i @ Wl4
__device__ float g_tF[(size_t)NF * HD];    // f @ Wl6

__device__ float g_pb[2][(size_t)NP * HD]; // ping-pong node features
__device__ float g_ab[2][(size_t)NA * HD];
__device__ float g_ib[2][(size_t)NI * HD];
__device__ float g_fb[2][(size_t)NF * HD];

__device__ float g_WrP[2 * HD * HD];       // combined Wr for paper (r0+r1+r6), per layer
__device__ float g_WrA[2 * HD * HD];       // combined Wr for author (r2+r4)
__device__ float g_bP[2 * HD];
__device__ float g_bA[2 * HD];

// CSR scratch: cnt doubles as cursor after scan
__device__ int g_cnt_c[NP];   __device__ int g_off_c[NP + 1];   __device__ int g_adj_c[E_C];
__device__ int g_cnt_w[NP];   __device__ int g_off_w[NP + 1];   __device__ int g_adj_w[E_W];
__device__ int g_cnt_rw[NA];  __device__ int g_off_rw[NA + 1];  __device__ int g_adj_rw[E_W];
__device__ int g_cnt_af[NI];  __device__ int g_off_af[NI + 1];  __device__ int g_adj_af[E_A];
__device__ int g_cnt_raf[NA]; __device__ int g_off_raf[NA + 1]; __device__ int g_adj_raf[E_A];
__device__ int g_cnt_t[NF];   __device__ int g_off_t[NF + 1];   __device__ int g_adj_t[E_T];
__device__ int g_cnt_rt[NP];  __device__ int g_off_rt[NP + 1];  __device__ int g_adj_rt[E_T];

// ---------------- small kernels ----------------
__global__ void hist_kernel(const int* __restrict__ dst, int E, int* cnt) {
    int i = blockIdx.x * blockDim.x + threadIdx.x;
    if (i < E) atomicAdd(&cnt[dst[i]], 1);
}

__global__ void scan_kernel(int* cnt, int n, int* offs) {
    __shared__ int sh[1024];
    int tid = threadIdx.x;
    int chunk = (n + 1023) >> 10;
    int beg = tid * chunk;
    int end = beg + chunk; if (end > n) end = n;
    int s = 0;
    for (int i = beg; i < end; i++) s += cnt[i];
    sh[tid] = s;
    __syncthreads();
    for (int d = 1; d < 1024; d <<= 1) {
        int t = (tid >= d) ? sh[tid - d] : 0;
        __syncthreads();
        sh[tid] += t;
        __syncthreads();
    }
    int run = sh[tid] - s;
    for (int i = beg; i < end; i++) {
        int c = cnt[i];
        offs[i] = run;
        cnt[i]  = run;
        run += c;
    }
    if (beg < n && end == n) offs[n] = run;
}

__global__ void fill_kernel(const int* __restrict__ src, const int* __restrict__ dst,
                            int E, int* cursor, int* __restrict__ adj) {
    int i = blockIdx.x * blockDim.x + threadIdx.x;
    if (i < E) {
        int p = atomicAdd(&cursor[dst[i]], 1);
        adj[p] = src[i];
    }
}

// mean aggregation: 64 threads per dst node (float4 per thread), 4 nodes per block
__global__ void gather_mean_kernel(const float* __restrict__ x,
                                   const int* __restrict__ offs,
                                   const int* __restrict__ adj,
                                   float* __restrict__ out, int n_dst) {
    int node = blockIdx.x * 4 + (threadIdx.x >> 6);
    int lane = threadIdx.x & 63;
    if (node >= n_dst) return;
    int beg = offs[node], end = offs[node + 1];
    float4 acc = make_float4(0.f, 0.f, 0.f, 0.f);
    int e = beg;
    for (; e + 1 < end; e += 2) {
        int s0 = adj[e], s1 = adj[e + 1];
        float4 v0 = ((const float4*)(x + (size_t)s0 * HD))[lane];
        float4 v1 = ((const float4*)(x + (size_t)s1 * HD))[lane];
        acc.x += v0.x + v1.x; acc.y += v0.y + v1.y;
        acc.z += v0.z + v1.z; acc.w += v0.w + v1.w;
    }
    if (e < end) {
        float4 v = ((const float4*)(x + (size_t)adj[e] * HD))[lane];
        acc.x += v.x; acc.y += v.y; acc.z += v.z; acc.w += v.w;
    }
    float inv = (end > beg) ? 1.f / (float)(end - beg) : 0.f;
    float4 r = make_float4(acc.x * inv, acc.y * inv, acc.z * inv, acc.w * inv);
    ((float4*)(out + (size_t)node * HD))[lane] = r;
}

__global__ void combine_kernel(const float* __restrict__ Wr, const float* __restrict__ bl,
                               float* __restrict__ WrP, float* __restrict__ WrA,
                               float* __restrict__ bP, float* __restrict__ bA) {
    int idx = blockIdx.x * blockDim.x + threadIdx.x;
    if (idx < 2 * HD * HD) {
        int l = idx / (HD * HD), j = idx % (HD * HD);
        const float* base = Wr + (size_t)l * 7 * HD * HD;
        WrP[idx] = base[0 * HD * HD + j] + base[1 * HD * HD + j] + base[6 * HD * HD + j];
        WrA[idx] = base[2 * HD * HD + j] + base[4 * HD * HD + j];
    }
    if (idx < 2 * HD) {
        int l = idx / HD, j = idx % HD;
        const float* bb = bl + (size_t)l * 7 * HD;
        bP[idx] = bb[0 * HD + j] + bb[1 * HD + j] + bb[6 * HD + j];
        bA[idx] = bb[2 * HD + j] + bb[4 * HD + j];
    }
}

// ---------------- tf32 tensor-core multi-part GEMM -----------------------------
// C[M,N] = act( sum_p A_p[M,256] @ W_p[256,N] + bias + add0 + add1 )
// A stored in smem in MMA-fragment order -> one LDS.128 per A fragment.
struct GemmArgs {
    const float* A[2];
    const float* W[2];
    const float* add0; const float* add1;
    const float* bias;
    float* C;
    int nparts, nadd, M, N, relu;
};

__device__ __forceinline__ float to_tf32(float x) {
    uint32_t u;
    asm("cvt.rna.tf32.f32 %0, %1;" : "=r"(u) : "f"(x));
    return __uint_as_float(u);
}

__device__ __forceinline__ void mma_tf32(float* c, const uint32_t* a, const uint32_t* b) {
    asm volatile(
        "mma.sync.aligned.m16n8k8.row.col.f32.tf32.tf32.f32 "
        "{%0,%1,%2,%3}, {%4,%5,%6,%7}, {%8,%9}, {%0,%1,%2,%3};\n"
        : "+f"(c[0]), "+f"(c[1]), "+f"(c[2]), "+f"(c[3])
        : "r"(a[0]), "r"(a[1]), "r"(a[2]), "r"(a[3]), "r"(b[0]), "r"(b[1]));
}

#define BK 32
#define APITCH 136  // B pitch: fragment scalar loads conflict-free

// A fragment buffer: 32 regions (ks[4] x warp_m[2] x i[4]) of 128 floats.
// Within region: unit u = gq*4 + tig (swizzled u^=u>>3), 4 reg slots,
// slot r = (m>>3)&1 | ((k>>2)&1)<<1, stored at r' = r ^ (2*(i&1)).

__global__ __launch_bounds__(256) void gemm_tf32_kernel(GemmArgs g) {
    __shared__ float Af[4096];        // A fragments, 16 KB
    __shared__ float Bs[BK][APITCH];  // k-major: Bs[k][n]

    int tid = threadIdx.x;
    int bm = blockIdx.y * 128;
    int bn = blockIdx.x * 128;
    int warp = tid >> 5, lane = tid & 31;
    int warp_m = warp >> 2;          // 0..1  -> 64 rows each
    int warp_n = warp & 3;           // 0..3  -> 32 cols each
    int gq = lane >> 2, tig = lane & 3;
    int ulsw = (lane ^ (lane >> 3)) * 4;   // consumer unit-swizzled float offset

    // A loader: thread covers row lm, 16 consecutive k at lk*16
    int lm = tid & 127;
    int lk = tid >> 7;               // 0/1
    bool arow_ok = (bm + lm) < g.M;
    int wml = lm >> 6;               // loader's warp_m region
    int il  = (lm >> 4) & 3;         // loader's i region
    int gql = lm & 7;
    int rb0 = (lm >> 3) & 1;
    int rsw = (il & 1) << 1;         // reg-slot swizzle for odd i

    // B loader: thread covers 4 cols at nc, k rows kr+{0,8,16,24}
    int nc = (tid & 31) * 4;
    int kr = tid >> 5;               // 0..7

    float acc[4][4][4];
#pragma unroll
    for (int i = 0; i < 4; i++)
#pragma unroll
        for (int j = 0; j < 4; j++)
#pragma unroll
            for (int q = 0; q < 4; q++) acc[i][j][q] = 0.f;

    for (int p = 0; p < g.nparts; p++) {
        const float* A = g.A[p];
        const float* W = g.W[p];
        for (int k0 = 0; k0 < HD; k0 += BK) {
            // ---- load A tile into fragment layout ----
            const float* Arow = A + (size_t)(bm + lm) * HD + k0 + lk * 16;
#pragma unroll
            for (int ii = 0; ii < 4; ii++) {
                float4 v = make_float4(0.f, 0.f, 0.f, 0.f);
                if (arow_ok) v = *(const float4*)(Arow + ii * 4);
                float vv[4] = { v.x, v.y, v.z, v.w };
#pragma unroll
                for (int cc = 0; cc < 4; cc++) {
                    int kk = lk * 16 + ii * 4 + cc;       // 0..31 within chunk
                    int ks = kk >> 3;
                    int tg = kk & 3;
                    int rb1 = (kk >> 2) & 1;
                    int r  = rb0 | (rb1 << 1);
                    int rp = r ^ rsw;
                    int u  = gql * 4 + tg;
                    int up = u ^ (u >> 3);
                    Af[(((ks * 2 + wml) * 4 + il) << 7) + up * 4 + rp] = to_tf32(vv[cc]);
                }
            }
            // ---- load B tile (k-major; scalar loads: N=349 rows unaligned) ----
#pragma unroll
            for (int i = 0; i < 4; i++) {
                int krow = kr + i * 8;
                const float* Wp = W + (size_t)(k0 + krow) * g.N + bn + nc;
                float4 v;
                v.x = (bn + nc + 0 < g.N) ? Wp[0] : 0.f;
                v.y = (bn + nc + 1 < g.N) ? Wp[1] : 0.f;
                v.z = (bn + nc + 2 < g.N) ? Wp[2] : 0.f;
                v.w = (bn + nc + 3 < g.N) ? Wp[3] : 0.f;
                v.x = to_tf32(v.x); v.y = to_tf32(v.y);
                v.z = to_tf32(v.z); v.w = to_tf32(v.w);
                *(float4*)(&Bs[krow][nc]) = v;
            }
            __syncthreads();

            // ---- 4 k8-steps of m16n8k8 tf32 mma ----
#pragma unroll
            for (int ks = 0; ks < 4; ks++) {
                int kb = ks * 8;
                uint32_t afr[4][4];
#pragma unroll
                for (int i = 0; i < 4; i++) {
                    const float4 av = *(const float4*)(
                        Af + (((ks * 2 + warp_m) * 4 + i) << 7) + ulsw);
                    if ((i & 1) == 0) {
                        afr[i][0] = __float_as_uint(av.x);
                        afr[i][1] = __float_as_uint(av.y);
                        afr[i][2] = __float_as_uint(av.z);
                        afr[i][3] = __float_as_uint(av.w);
                    } else {  // undo r' = r ^ 2 swizzle
                        afr[i][0] = __float_as_uint(av.z);
                        afr[i][1] = __float_as_uint(av.w);
                        afr[i][2] = __float_as_uint(av.x);
                        afr[i][3] = __float_as_uint(av.y);
                    }
                }
                uint32_t bfr[4][2];
#pragma unroll
                for (int j = 0; j < 4; j++) {
                    int nb = warp_n * 32 + j * 8;
                    bfr[j][0] = __float_as_uint(Bs[kb + tig][nb + gq]);
                    bfr[j][1] = __float_as_uint(Bs[kb + tig + 4][nb + gq]);
                }
#pragma unroll
                for (int i = 0; i < 4; i++)
#pragma unroll
                    for (int j = 0; j < 4; j++)
                        mma_tf32(acc[i][j], afr[i], bfr[j]);
            }
            __syncthreads();
        }
    }

    // ---- epilogue: addends + bias + relu + guarded store ----
#pragma unroll
    for (int i = 0; i < 4; i++) {
        int r0 = bm + warp_m * 64 + i * 16 + gq;
        int r1 = r0 + 8;
#pragma unroll
        for (int j = 0; j < 4; j++) {
            int c0 = bn + warp_n * 32 + j * 8 + tig * 2;
            bool c0ok = c0 < g.N, c1ok = (c0 + 1) < g.N;
            float bia0 = 0.f, bia1 = 0.f;
            if (g.bias) {
                if (c0ok) bia0 = g.bias[c0];
                if (c1ok) bia1 = g.bias[c0 + 1];
            }
            float v00 = acc[i][j][0] + bia0, v01 = acc[i][j][1] + bia1;
            float v10 = acc[i][j][2] + bia0, v11 = acc[i][j][3] + bia1;
            if (g.nadd > 0) {
                const float* a0p = g.add0;
                if (r0 < g.M) {
                    if (c0ok) v00 += a0p[(size_t)r0 * g.N + c0];
                    if (c1ok) v01 += a0p[(size_t)r0 * g.N + c0 + 1];
                }
                if (r1 < g.M) {
                    if (c0ok) v10 += a0p[(size_t)r1 * g.N + c0];
                    if (c1ok) v11 += a0p[(size_t)r1 * g.N + c0 + 1];
                }
            }
            if (g.nadd > 1) {
                const float* a1p = g.add1;
                if (r0 < g.M) {
                    if (c0ok) v00 += a1p[(size_t)r0 * g.N + c0];
                    if (c1ok) v01 += a1p[(size_t)r0 * g.N + c0 + 1];
                }
                if (r1 < g.M) {
                    if (c0ok) v10 += a1p[(size_t)r1 * g.N + c0];
                    if (c1ok) v11 += a1p[(size_t)r1 * g.N + c0 + 1];
                }
            }
            if (g.relu) {
                v00 = v00 > 0.f ? v00 : 0.f; v01 = v01 > 0.f ? v01 : 0.f;
                v10 = v10 > 0.f ? v10 : 0.f; v11 = v11 > 0.f ? v11 : 0.f;
            }
            if (r0 < g.M) {
                if (c0ok) g.C[(size_t)r0 * g.N + c0]     = v00;
                if (c1ok) g.C[(size_t)r0 * g.N + c0 + 1] = v01;
            }
            if (r1 < g.M) {
                if (c0ok) g.C[(size_t)r1 * g.N + c0]     = v10;
                if (c1ok) g.C[(size_t)r1 * g.N + c0 + 1] = v11;
            }
        }
    }
}

// ---------------- host ----------------
static inline int cdiv(int a, int b) { return (a + b - 1) / b; }

static void launch_gemm(int M, int N, int nparts,
                        const float* A0, const float* W0,
                        const float* A1, const float* W1,
                        int nadd, const float* add0, const float* add1,
                        const float* bias, float* C, int relu) {
    GemmArgs g;
    g.A[0] = A0; g.A[1] = A1; g.W[0] = W0; g.W[1] = W1;
    g.add0 = add0; g.add1 = add1;
    g.nparts = nparts; g.nadd = nadd; g.M = M; g.N = N;
    g.bias = bias; g.C = C; g.relu = relu;
    dim3 grid(cdiv(N, 128), cdiv(M, 128));
    gemm_tf32_kernel<<<grid, 256>>>(g);
}

extern "C" void kernel_launch(void* const* d_in, const int* in_sizes, int n_in,
                              void* d_out, int out_size) {
    const float* xp = (const float*)d_in[0];
    const float* xa = (const float*)d_in[1];
    const float* xi = (const float*)d_in[2];
    const float* xf = (const float*)d_in[3];
    const int* cites_src = (const int*)d_in[4];
    const int* cites_dst = (const int*)d_in[5];
    const int* writes_src = (const int*)d_in[6];
    const int* writes_dst = (const int*)d_in[7];
    const int* rwrites_src = (const int*)d_in[8];
    const int* rwrites_dst = (const int*)d_in[9];
    const int* aff_src = (const int*)d_in[10];
    const int* aff_dst = (const int*)d_in[11];
    const int* raff_src = (const int*)d_in[12];
    const int* raff_dst = (const int*)d_in[13];
    const int* topic_src = (const int*)d_in[14];
    const int* topic_dst = (const int*)d_in[15];
    const int* rtopic_src = (const int*)d_in[16];
    const int* rtopic_dst = (const int*)d_in[17];
    const float* Wl = (const float*)d_in[18];
    const float* bl = (const float*)d_in[19];
    const float* Wr = (const float*)d_in[20];
    const float* Wout = (const float*)d_in[21];
    const float* bout = (const float*)d_in[22];

    float *m0, *gg1, *gg6, *ma2, *gg4, *mi3, *mf5, *tA, *tI, *tF;
    float *pb, *ab, *ib, *fb, *WrP, *WrA, *bP, *bA;
    int *cnt_c, *off_c, *adj_c, *cnt_w, *off_w, *adj_w;
    int *cnt_rw, *off_rw, *adj_rw, *cnt_af, *off_af, *adj_af;
    int *cnt_raf, *off_raf, *adj_raf, *cnt_t, *off_t, *adj_t;
    int *cnt_rt, *off_rt, *adj_rt;
    cudaGetSymbolAddress((void**)&m0, g_mp0);
    cudaGetSymbolAddress((void**)&gg1, g_mp1);
    cudaGetSymbolAddress((void**)&gg6, g_mp6);
    cudaGetSymbolAddress((void**)&ma2, g_ma2);
    cudaGetSymbolAddress((void**)&gg4, g_ma4);
    cudaGetSymbolAddress((void**)&mi3, g_mi3);
    cudaGetSymbolAddress((void**)&mf5, g_mf5);
    cudaGetSymbolAddress((void**)&tA, g_tA);
    cudaGetSymbolAddress((void**)&tI, g_tI);
    cudaGetSymbolAddress((void**)&tF, g_tF);
    cudaGetSymbolAddress((void**)&pb, g_pb);
    cudaGetSymbolAddress((void**)&ab, g_ab);
    cudaGetSymbolAddress((void**)&ib, g_ib);
    cudaGetSymbolAddress((void**)&fb, g_fb);
    cudaGetSymbolAddress((void**)&WrP, g_WrP);
    cudaGetSymbolAddress((void**)&WrA, g_WrA);
    cudaGetSymbolAddress((void**)&bP, g_bP);
    cudaGetSymbolAddress((void**)&bA, g_bA);
    cudaGetSymbolAddress((void**)&cnt_c, g_cnt_c);
    cudaGetSymbolAddress((void**)&off_c, g_off_c);
    cudaGetSymbolAddress((void**)&adj_c, g_adj_c);
    cudaGetSymbolAddress((void**)&cnt_w, g_cnt_w);
    cudaGetSymbolAddress((void**)&off_w, g_off_w);
    cudaGetSymbolAddress((void**)&adj_w, g_adj_w);
    cudaGetSymbolAddress((void**)&cnt_rw, g_cnt_rw);
    cudaGetSymbolAddress((void**)&off_rw, g_off_rw);
    cudaGetSymbolAddress((void**)&adj_rw, g_adj_rw);
    cudaGetSymbolAddress((void**)&cnt_af, g_cnt_af);
    cudaGetSymbolAddress((void**)&off_af, g_off_af);
    cudaGetSymbolAddress((void**)&adj_af, g_adj_af);
    cudaGetSymbolAddress((void**)&cnt_raf, g_cnt_raf);
    cudaGetSymbolAddress((void**)&off_raf, g_off_raf);
    cudaGetSymbolAddress((void**)&adj_raf, g_adj_raf);
    cudaGetSymbolAddress((void**)&cnt_t, g_cnt_t);
    cudaGetSymbolAddress((void**)&off_t, g_off_t);
    cudaGetSymbolAddress((void**)&adj_t, g_adj_t);
    cudaGetSymbolAddress((void**)&cnt_rt, g_cnt_rt);
    cudaGetSymbolAddress((void**)&off_rt, g_off_rt);
    cudaGetSymbolAddress((void**)&adj_rt, g_adj_rt);

    float* pbuf[2] = { pb, pb + (size_t)NP * HD };
    float* abuf[2] = { ab, ab + (size_t)NA * HD };
    float* ibuf[2] = { ib, ib + (size_t)NI * HD };
    float* fbuf[2] = { fb, fb + (size_t)NF * HD };

    // ---- build CSR for all 7 relations (reused by both layers) ----
    struct Rel { const int* src; const int* dst; int E; int n_dst; int* cnt; int* off; int* adj; };
    Rel rels[7] = {
        { cites_src,   cites_dst,   E_C, NP, cnt_c,   off_c,   adj_c   },
        { writes_src,  writes_dst,  E_W, NP, cnt_w,   off_w,   adj_w   },
        { rwrites_src, rwrites_dst, E_W, NA, cnt_rw,  off_rw,  adj_rw  },
        { aff_src,     aff_dst,     E_A, NI, cnt_af,  off_af,  adj_af  },
        { raff_src,    raff_dst,    E_A, NA, cnt_raf, off_raf, adj_raf },
        { topic_src,   topic_dst,   E_T, NF, cnt_t,   off_t,   adj_t   },
        { rtopic_src,  rtopic_dst,  E_T, NP, cnt_rt,  off_rt,  adj_rt  },
    };
    for (int r = 0; r < 7; r++) {
        cudaMemsetAsync(rels[r].cnt, 0, (size_t)rels[r].n_dst * sizeof(int), 0);
        hist_kernel<<<cdiv(rels[r].E, 256), 256>>>(rels[r].dst, rels[r].E, rels[r].cnt);
        scan_kernel<<<1, 1024>>>(rels[r].cnt, rels[r].n_dst, rels[r].off);
        fill_kernel<<<cdiv(rels[r].E, 256), 256>>>(rels[r].src, rels[r].dst, rels[r].E,
                                                   rels[r].cnt, rels[r].adj);
    }

    combine_kernel<<<cdiv(2 * HD * HD, 256), 256>>>(Wr, bl, WrP, WrA, bP, bA);

    // ---- 2 SAGE layers (smart-side: transform small side first, gather after) ----
    const float* cp = xp; const float* ca = xa; const float* ci = xi; const float* cf = xf;
    for (int l = 0; l < 2; l++) {
        const size_t WSZ = (size_t)HD * HD;
        const float* WlL = Wl + (size_t)l * 7 * WSZ;
        const float* blL = bl + (size_t)l * 7 * HD;

        // src-side transforms (linearity: mean(x)@W == mean(x@W))
        launch_gemm(NA, HD, 1, ca, WlL + 1 * WSZ, 0, 0, 0, 0, 0, 0, tA, 0);
        launch_gemm(NF, HD, 1, cf, WlL + 6 * WSZ, 0, 0, 0, 0, 0, 0, tF, 0);
        launch_gemm(NI, HD, 1, ci, WlL + 4 * WSZ, 0, 0, 0, 0, 0, 0, tI, 0);

        // gathers
        gather_mean_kernel<<<cdiv(NP, 4), 256>>>(cp, off_c,   adj_c,   m0,  NP);  // raw
        gather_mean_kernel<<<cdiv(NP, 4), 256>>>(tA, off_w,   adj_w,   gg1, NP);  // transformed
        gather_mean_kernel<<<cdiv(NP, 4), 256>>>(tF, off_rt,  adj_rt,  gg6, NP);  // transformed
        gather_mean_kernel<<<cdiv(NA, 4), 256>>>(cp, off_rw,  adj_rw,  ma2, NA);  // raw
        gather_mean_kernel<<<cdiv(NA, 4), 256>>>(tI, off_raf, adj_raf, gg4, NA);  // transformed
        gather_mean_kernel<<<cdiv(NI, 4), 256>>>(ca, off_af,  adj_af,  mi3, NI);  // raw
        gather_mean_kernel<<<cdiv(NF, 4), 256>>>(cp, off_t,   adj_t,   mf5, NF);  // raw

        // output GEMMs
        // new_p = relu(m0@Wl0 + p@WrP + bP + g1 + g6)
        launch_gemm(NP, HD, 2, m0, WlL + 0 * WSZ, cp, WrP + (size_t)l * WSZ,
                    2, gg1, gg6, bP + (size_t)l * HD, pbuf[l], 1);
        // new_a = relu(ma2@Wl2 + a@WrA + bA + g4)
        launch_gemm(NA, HD, 2, ma2, WlL + 2 * WSZ, ca, WrA + (size_t)l * WSZ,
                    1, gg4, 0, bA + (size_t)l * HD, abuf[l], 1);
        // new_i = relu(mi3@Wl3 + i@Wr3 + bl3)
        launch_gemm(NI, HD, 2, mi3, WlL + 3 * WSZ, ci, Wr + ((size_t)l * 7 + 3) * WSZ,
                    0, 0, 0, blL + 3 * HD, ibuf[l], 1);
        // new_f = relu(mf5@Wl5 + f@Wr5 + bl5)
        launch_gemm(NF, HD, 2, mf5, WlL + 5 * WSZ, cf, Wr + ((size_t)l * 7 + 5) * WSZ,
                    0, 0, 0, blL + 5 * HD, fbuf[l], 1);

        cp = pbuf[l]; ca = abuf[l]; ci = ibuf[l]; cf = fbuf[l];
    }

    // ---- final projection: out = p @ W_out + b_out ----
    launch_gemm(NP, NOUT, 1, cp, Wout, 0, 0, 0, 0, 0, bout, (float*)d_out, 0);
}

// round 15
// speedup vs baseline: 1.2374x; 1.1668x over previous
#include <cuda_runtime.h>
#include <cstdint>

#define NP 200000
#define NA 100000
#define NI 8000
#define NF 30000
#define HD 256
#define NOUT 349
#define E_C 500000
#define E_W 400000
#define E_A 100000
#define E_T 300000

// ---------------- scratch (static device allocations, allowed) ----------------
__device__ float g_mp0[(size_t)NP * HD];   // m0: mean cites(p) raw
__device__ float g_mp1[(size_t)NP * HD];   // g1: mean writes(a@Wl1)
__device__ float g_mp6[(size_t)NP * HD];   // g6: mean rev_topic(f@Wl6)
__device__ float g_ma2[(size_t)NA * HD];   // ma2: mean rev_writes(p) raw
__device__ float g_ma4[(size_t)NA * HD];   // g4: mean rev_aff(i@Wl4)
__device__ float g_mf5[(size_t)NF * HD];   // mf5: mean topic(p) raw

__device__ float g_tA[(size_t)NA * HD];    // a @ Wl1
__device__ float g_tI[(size_t)NI * HD];    // i @ Wl4
__device__ float g_tF[(size_t)NF * HD];    // f @ Wl6

__device__ float g_p1[(size_t)NP * HD];    // layer-1 paper
__device__ float g_p2[(size_t)NP * HD];    // layer-2 paper
__device__ float g_a1[(size_t)NA * HD];    // layer-1 author
__device__ float g_f1[(size_t)NF * HD];    // layer-1 fos

__device__ float g_WrP[2 * HD * HD];       // combined Wr for paper (r0+r1+r6), per layer
__device__ float g_WrA[2 * HD * HD];       // combined Wr for author (r2+r4)
__device__ float g_bP[2 * HD];
__device__ float g_bA[2 * HD];

// CSR scratch: cnt doubles as cursor after scan
__device__ int g_cnt_c[NP];   __device__ int g_off_c[NP + 1];   __device__ int g_adj_c[E_C];
__device__ int g_cnt_w[NP];   __device__ int g_off_w[NP + 1];   __device__ int g_adj_w[E_W];
__device__ int g_cnt_rw[NA];  __device__ int g_off_rw[NA + 1];  __device__ int g_adj_rw[E_W];
__device__ int g_cnt_raf[NA]; __device__ int g_off_raf[NA + 1]; __device__ int g_adj_raf[E_A];
__device__ int g_cnt_t[NF];   __device__ int g_off_t[NF + 1];   __device__ int g_adj_t[E_T];
__device__ int g_cnt_rt[NP];  __device__ int g_off_rt[NP + 1];  __device__ int g_adj_rt[E_T];

// ---------------- small kernels ----------------
__global__ void hist_kernel(const int* __restrict__ dst, int E, int* cnt) {
    int i = blockIdx.x * blockDim.x + threadIdx.x;
    if (i < E) atomicAdd(&cnt[dst[i]], 1);
}

__global__ void scan_kernel(int* cnt, int n, int* offs) {
    __shared__ int sh[1024];
    int tid = threadIdx.x;
    int chunk = (n + 1023) >> 10;
    int beg = tid * chunk;
    int end = beg + chunk; if (end > n) end = n;
    int s = 0;
    for (int i = beg; i < end; i++) s += cnt[i];
    sh[tid] = s;
    __syncthreads();
    for (int d = 1; d < 1024; d <<= 1) {
        int t = (tid >= d) ? sh[tid - d] : 0;
        __syncthreads();
        sh[tid] += t;
        __syncthreads();
    }
    int run = sh[tid] - s;
    for (int i = beg; i < end; i++) {
        int c = cnt[i];
        offs[i] = run;
        cnt[i]  = run;
        run += c;
    }
    if (beg < n && end == n) offs[n] = run;
}

__global__ void fill_kernel(const int* __restrict__ src, const int* __restrict__ dst,
                            int E, int* cursor, int* __restrict__ adj) {
    int i = blockIdx.x * blockDim.x + threadIdx.x;
    if (i < E) {
        int p = atomicAdd(&cursor[dst[i]], 1);
        adj[p] = src[i];
    }
}

// mean aggregation: 64 threads per dst node (float4 per thread), 4 nodes per block
__global__ void gather_mean_kernel(const float* __restrict__ x,
                                   const int* __restrict__ offs,
                                   const int* __restrict__ adj,
                                   float* __restrict__ out, int n_dst) {
    int node = blockIdx.x * 4 + (threadIdx.x >> 6);
    int lane = threadIdx.x & 63;
    if (node >= n_dst) return;
    int beg = offs[node], end = offs[node + 1];
    float4 acc = make_float4(0.f, 0.f, 0.f, 0.f);
    int e = beg;
    for (; e + 1 < end; e += 2) {
        int s0 = adj[e], s1 = adj[e + 1];
        float4 v0 = ((const float4*)(x + (size_t)s0 * HD))[lane];
        float4 v1 = ((const float4*)(x + (size_t)s1 * HD))[lane];
        acc.x += v0.x + v1.x; acc.y += v0.y + v1.y;
        acc.z += v0.z + v1.z; acc.w += v0.w + v1.w;
    }
    if (e < end) {
        float4 v = ((const float4*)(x + (size_t)adj[e] * HD))[lane];
        acc.x += v.x; acc.y += v.y; acc.z += v.z; acc.w += v.w;
    }
    float inv = (end > beg) ? 1.f / (float)(end - beg) : 0.f;
    float4 r = make_float4(acc.x * inv, acc.y * inv, acc.z * inv, acc.w * inv);
    ((float4*)(out + (size_t)node * HD))[lane] = r;
}

__global__ void combine_kernel(const float* __restrict__ Wr, const float* __restrict__ bl,
                               float* __restrict__ WrP, float* __restrict__ WrA,
                               float* __restrict__ bP, float* __restrict__ bA) {
    int idx = blockIdx.x * blockDim.x + threadIdx.x;
    if (idx < 2 * HD * HD) {
        int l = idx / (HD * HD), j = idx % (HD * HD);
        const float* base = Wr + (size_t)l * 7 * HD * HD;
        WrP[idx] = base[0 * HD * HD + j] + base[1 * HD * HD + j] + base[6 * HD * HD + j];
        WrA[idx] = base[2 * HD * HD + j] + base[4 * HD * HD + j];
    }
    if (idx < 2 * HD) {
        int l = idx / HD, j = idx % HD;
        const float* bb = bl + (size_t)l * 7 * HD;
        bP[idx] = bb[0 * HD + j] + bb[1 * HD + j] + bb[6 * HD + j];
        bA[idx] = bb[2 * HD + j] + bb[4 * HD + j];
    }
}

// ---------------- tf32 tensor-core multi-part GEMM (R13 proven) ----------------
// C[M,N] = act( sum_p A_p[M,256] @ W_p[256,N] + bias + add0 + add1 )
// A stored in smem in MMA-fragment order -> one LDS.128 per A fragment.
struct GemmArgs {
    const float* A[2];
    const float* W[2];
    const float* add0; const float* add1;
    const float* bias;
    float* C;
    int nparts, nadd, M, N, relu;
};

__device__ __forceinline__ float to_tf32(float x) {
    uint32_t u;
    asm("cvt.rna.tf32.f32 %0, %1;" : "=r"(u) : "f"(x));
    return __uint_as_float(u);
}

__device__ __forceinline__ void mma_tf32(float* c, const uint32_t* a, const uint32_t* b) {
    asm volatile(
        "mma.sync.aligned.m16n8k8.row.col.f32.tf32.tf32.f32 "
        "{%0,%1,%2,%3}, {%4,%5,%6,%7}, {%8,%9}, {%0,%1,%2,%3};\n"
        : "+f"(c[0]), "+f"(c[1]), "+f"(c[2]), "+f"(c[3])
        : "r"(a[0]), "r"(a[1]), "r"(a[2]), "r"(a[3]), "r"(b[0]), "r"(b[1]));
}

#define BK 32
#define APITCH 136  // B pitch: fragment scalar loads conflict-free

__global__ __launch_bounds__(256) void gemm_tf32_kernel(GemmArgs g) {
    __shared__ float Af[4096];        // A fragments, 16 KB
    __shared__ float Bs[BK][APITCH];  // k-major: Bs[k][n]

    int tid = threadIdx.x;
    int bm = blockIdx.y * 128;
    int bn = blockIdx.x * 128;
    int warp = tid >> 5, lane = tid & 31;
    int warp_m = warp >> 2;          // 0..1  -> 64 rows each
    int warp_n = warp & 3;           // 0..3  -> 32 cols each
    int gq = lane >> 2, tig = lane & 3;
    int ulsw = (lane ^ (lane >> 3)) * 4;   // consumer unit-swizzled float offset

    int lm = tid & 127;
    int lk = tid >> 7;               // 0/1
    bool arow_ok = (bm + lm) < g.M;
    int wml = lm >> 6;
    int il  = (lm >> 4) & 3;
    int gql = lm & 7;
    int rb0 = (lm >> 3) & 1;
    int rsw = (il & 1) << 1;

    int nc = (tid & 31) * 4;
    int kr = tid >> 5;               // 0..7

    float acc[4][4][4];
#pragma unroll
    for (int i = 0; i < 4; i++)
#pragma unroll
        for (int j = 0; j < 4; j++)
#pragma unroll
            for (int q = 0; q < 4; q++) acc[i][j][q] = 0.f;

    for (int p = 0; p < g.nparts; p++) {
        const float* A = g.A[p];
        const float* W = g.W[p];
        for (int k0 = 0; k0 < HD; k0 += BK) {
            const float* Arow = A + (size_t)(bm + lm) * HD + k0 + lk * 16;
#pragma unroll
            for (int ii = 0; ii < 4; ii++) {
                float4 v = make_float4(0.f, 0.f, 0.f, 0.f);
                if (arow_ok) v = *(const float4*)(Arow + ii * 4);
                float vv[4] = { v.x, v.y, v.z, v.w };
#pragma unroll
                for (int cc = 0; cc < 4; cc++) {
                    int kk = lk * 16 + ii * 4 + cc;
                    int ks = kk >> 3;
                    int tg = kk & 3;
                    int rb1 = (kk >> 2) & 1;
                    int r  = rb0 | (rb1 << 1);
                    int rp = r ^ rsw;
                    int u  = gql * 4 + tg;
                    int up = u ^ (u >> 3);
                    Af[(((ks * 2 + wml) * 4 + il) << 7) + up * 4 + rp] = to_tf32(vv[cc]);
                }
            }
#pragma unroll
            for (int i = 0; i < 4; i++) {
                int krow = kr + i * 8;
                const float* Wp = W + (size_t)(k0 + krow) * g.N + bn + nc;
                float4 v;
                v.x = (bn + nc + 0 < g.N) ? Wp[0] : 0.f;
                v.y = (bn + nc + 1 < g.N) ? Wp[1] : 0.f;
                v.z = (bn + nc + 2 < g.N) ? Wp[2] : 0.f;
                v.w = (bn + nc + 3 < g.N) ? Wp[3] : 0.f;
                v.x = to_tf32(v.x); v.y = to_tf32(v.y);
                v.z = to_tf32(v.z); v.w = to_tf32(v.w);
                *(float4*)(&Bs[krow][nc]) = v;
            }
            __syncthreads();

#pragma unroll
            for (int ks = 0; ks < 4; ks++) {
                int kb = ks * 8;
                uint32_t afr[4][4];
#pragma unroll
                for (int i = 0; i < 4; i++) {
                    const float4 av = *(const float4*)(
                        Af + (((ks * 2 + warp_m) * 4 + i) << 7) + ulsw);
                    if ((i & 1) == 0) {
                        afr[i][0] = __float_as_uint(av.x);
                        afr[i][1] = __float_as_uint(av.y);
                        afr[i][2] = __float_as_uint(av.z);
                        afr[i][3] = __float_as_uint(av.w);
                    } else {
                        afr[i][0] = __float_as_uint(av.z);
                        afr[i][1] = __float_as_uint(av.w);
                        afr[i][2] = __float_as_uint(av.x);
                        afr[i][3] = __float_as_uint(av.y);
                    }
                }
                uint32_t bfr[4][2];
#pragma unroll
                for (int j = 0; j < 4; j++) {
                    int nb = warp_n * 32 + j * 8;
                    bfr[j][0] = __float_as_uint(Bs[kb + tig][nb + gq]);
                    bfr[j][1] = __float_as_uint(Bs[kb + tig + 4][nb + gq]);
                }
#pragma unroll
                for (int i = 0; i < 4; i++)
#pragma unroll
                    for (int j = 0; j < 4; j++)
                        mma_tf32(acc[i][j], afr[i], bfr[j]);
            }
            __syncthreads();
        }
    }

    // ---- epilogue: addends + bias + relu + guarded store ----
#pragma unroll
    for (int i = 0; i < 4; i++) {
        int r0 = bm + warp_m * 64 + i * 16 + gq;
        int r1 = r0 + 8;
#pragma unroll
        for (int j = 0; j < 4; j++) {
            int c0 = bn + warp_n * 32 + j * 8 + tig * 2;
            bool c0ok = c0 < g.N, c1ok = (c0 + 1) < g.N;
            float bia0 = 0.f, bia1 = 0.f;
            if (g.bias) {
                if (c0ok) bia0 = g.bias[c0];
                if (c1ok) bia1 = g.bias[c0 + 1];
            }
            float v00 = acc[i][j][0] + bia0, v01 = acc[i][j][1] + bia1;
            float v10 = acc[i][j][2] + bia0, v11 = acc[i][j][3] + bia1;
            if (g.nadd > 0) {
                const float* a0p = g.add0;
                if (r0 < g.M) {
                    if (c0ok) v00 += a0p[(size_t)r0 * g.N + c0];
                    if (c1ok) v01 += a0p[(size_t)r0 * g.N + c0 + 1];
                }
                if (r1 < g.M) {
                    if (c0ok) v10 += a0p[(size_t)r1 * g.N + c0];
                    if (c1ok) v11 += a0p[(size_t)r1 * g.N + c0 + 1];
                }
            }
            if (g.nadd > 1) {
                const float* a1p = g.add1;
                if (r0 < g.M) {
                    if (c0ok) v00 += a1p[(size_t)r0 * g.N + c0];
                    if (c1ok) v01 += a1p[(size_t)r0 * g.N + c0 + 1];
                }
                if (r1 < g.M) {
                    if (c0ok) v10 += a1p[(size_t)r1 * g.N + c0];
                    if (c1ok) v11 += a1p[(size_t)r1 * g.N + c0 + 1];
                }
            }
            if (g.relu) {
                v00 = v00 > 0.f ? v00 : 0.f; v01 = v01 > 0.f ? v01 : 0.f;
                v10 = v10 > 0.f ? v10 : 0.f; v11 = v11 > 0.f ? v11 : 0.f;
            }
            if (r0 < g.M) {
                if (c0ok) g.C[(size_t)r0 * g.N + c0]     = v00;
                if (c1ok) g.C[(size_t)r0 * g.N + c0 + 1] = v01;
            }
            if (r1 < g.M) {
                if (c0ok) g.C[(size_t)r1 * g.N + c0]     = v10;
                if (c1ok) g.C[(size_t)r1 * g.N + c0 + 1] = v11;
            }
        }
    }
}

// ---------------- host ----------------
static inline int cdiv(int a, int b) { return (a + b - 1) / b; }

static void launch_gemm(int M, int N, int nparts,
                        const float* A0, const float* W0,
                        const float* A1, const float* W1,
                        int nadd, const float* add0, const float* add1,
                        const float* bias, float* C, int relu) {
    GemmArgs g;
    g.A[0] = A0; g.A[1] = A1; g.W[0] = W0; g.W[1] = W1;
    g.add0 = add0; g.add1 = add1;
    g.nparts = nparts; g.nadd = nadd; g.M = M; g.N = N;
    g.bias = bias; g.C = C; g.relu = relu;
    dim3 grid(cdiv(N, 128), cdiv(M, 128));
    gemm_tf32_kernel<<<grid, 256>>>(g);
}

extern "C" void kernel_launch(void* const* d_in, const int* in_sizes, int n_in,
                              void* d_out, int out_size) {
    const float* xp = (const float*)d_in[0];
    const float* xa = (const float*)d_in[1];
    const float* xi = (const float*)d_in[2];
    const float* xf = (const float*)d_in[3];
    const int* cites_src = (const int*)d_in[4];
    const int* cites_dst = (const int*)d_in[5];
    const int* writes_src = (const int*)d_in[6];
    const int* writes_dst = (const int*)d_in[7];
    const int* rwrites_src = (const int*)d_in[8];
    const int* rwrites_dst = (const int*)d_in[9];
    const int* raff_src = (const int*)d_in[12];
    const int* raff_dst = (const int*)d_in[13];
    const int* topic_src = (const int*)d_in[14];
    const int* topic_dst = (const int*)d_in[15];
    const int* rtopic_src = (const int*)d_in[16];
    const int* rtopic_dst = (const int*)d_in[17];
    const float* Wl = (const float*)d_in[18];
    const float* bl = (const float*)d_in[19];
    const float* Wr = (const float*)d_in[20];
    const float* Wout = (const float*)d_in[21];
    const float* bout = (const float*)d_in[22];

    float *m0, *gg1, *gg6, *ma2, *gg4, *mf5, *tA, *tI, *tF;
    float *p1, *p2, *a1, *f1, *WrP, *WrA, *bP, *bA;
    int *cnt_c, *off_c, *adj_c, *cnt_w, *off_w, *adj_w;
    int *cnt_rw, *off_rw, *adj_rw;
    int *cnt_raf, *off_raf, *adj_raf, *cnt_t, *off_t, *adj_t;
    int *cnt_rt, *off_rt, *adj_rt;
    cudaGetSymbolAddress((void**)&m0, g_mp0);
    cudaGetSymbolAddress((void**)&gg1, g_mp1);
    cudaGetSymbolAddress((void**)&gg6, g_mp6);
    cudaGetSymbolAddress((void**)&ma2, g_ma2);
    cudaGetSymbolAddress((void**)&gg4, g_ma4);
    cudaGetSymbolAddress((void**)&mf5, g_mf5);
    cudaGetSymbolAddress((void**)&tA, g_tA);
    cudaGetSymbolAddress((void**)&tI, g_tI);
    cudaGetSymbolAddress((void**)&tF, g_tF);
    cudaGetSymbolAddress((void**)&p1, g_p1);
    cudaGetSymbolAddress((void**)&p2, g_p2);
    cudaGetSymbolAddress((void**)&a1, g_a1);
    cudaGetSymbolAddress((void**)&f1, g_f1);
    cudaGetSymbolAddress((void**)&WrP, g_WrP);
    cudaGetSymbolAddress((void**)&WrA, g_WrA);
    cudaGetSymbolAddress((void**)&bP, g_bP);
    cudaGetSymbolAddress((void**)&bA, g_bA);
    cudaGetSymbolAddress((void**)&cnt_c, g_cnt_c);
    cudaGetSymbolAddress((void**)&off_c, g_off_c);
    cudaGetSymbolAddress((void**)&adj_c, g_adj_c);
    cudaGetSymbolAddress((void**)&cnt_w, g_cnt_w);
    cudaGetSymbolAddress((void**)&off_w, g_off_w);
    cudaGetSymbolAddress((void**)&adj_w, g_adj_w);
    cudaGetSymbolAddress((void**)&cnt_rw, g_cnt_rw);
    cudaGetSymbolAddress((void**)&off_rw, g_off_rw);
    cudaGetSymbolAddress((void**)&adj_rw, g_adj_rw);
    cudaGetSymbolAddress((void**)&cnt_raf, g_cnt_raf);
    cudaGetSymbolAddress((void**)&off_raf, g_off_raf);
    cudaGetSymbolAddress((void**)&adj_raf, g_adj_raf);
    cudaGetSymbolAddress((void**)&cnt_t, g_cnt_t);
    cudaGetSymbolAddress((void**)&off_t, g_off_t);
    cudaGetSymbolAddress((void**)&adj_t, g_adj_t);
    cudaGetSymbolAddress((void**)&cnt_rt, g_cnt_rt);
    cudaGetSymbolAddress((void**)&off_rt, g_off_rt);
    cudaGetSymbolAddress((void**)&adj_rt, g_adj_rt);

    // ---- build CSR (only the 6 relations that survive dead-code elim) ----
    struct Rel { const int* src; const int* dst; int E; int n_dst; int* cnt; int* off; int* adj; };
    Rel rels[6] = {
        { cites_src,   cites_dst,   E_C, NP, cnt_c,   off_c,   adj_c   },
        { writes_src,  writes_dst,  E_W, NP, cnt_w,   off_w,   adj_w   },
        { rwrites_src, rwrites_dst, E_W, NA, cnt_rw,  off_rw,  adj_rw  },
        { raff_src,    raff_dst,    E_A, NA, cnt_raf, off_raf, adj_raf },
        { topic_src,   topic_dst,   E_T, NF, cnt_t,   off_t,   adj_t   },
        { rtopic_src,  rtopic_dst,  E_T, NP, cnt_rt,  off_rt,  adj_rt  },
    };
    for (int r = 0; r < 6; r++) {
        cudaMemsetAsync(rels[r].cnt, 0, (size_t)rels[r].n_dst * sizeof(int), 0);
        hist_kernel<<<cdiv(rels[r].E, 256), 256>>>(rels[r].dst, rels[r].E, rels[r].cnt);
        scan_kernel<<<1, 1024>>>(rels[r].cnt, rels[r].n_dst, rels[r].off);
        fill_kernel<<<cdiv(rels[r].E, 256), 256>>>(rels[r].src, rels[r].dst, rels[r].E,
                                                   rels[r].cnt, rels[r].adj);
    }

    combine_kernel<<<cdiv(2 * HD * HD, 256), 256>>>(Wr, bl, WrP, WrA, bP, bA);

    const size_t WSZ = (size_t)HD * HD;
    const float* Wl0 = Wl;                     const float* bl0 = bl;
    const float* Wl1 = Wl + 7 * WSZ;

    // ================= LAYER 1 (paper, author, fos — institution output is dead) =====
    // src-side transforms (linearity: mean(x)@W == mean(x@W))
    launch_gemm(NA, HD, 1, xa, Wl0 + 1 * WSZ, 0, 0, 0, 0, 0, 0, tA, 0);
    launch_gemm(NF, HD, 1, xf, Wl0 + 6 * WSZ, 0, 0, 0, 0, 0, 0, tF, 0);
    launch_gemm(NI, HD, 1, xi, Wl0 + 4 * WSZ, 0, 0, 0, 0, 0, 0, tI, 0);

    gather_mean_kernel<<<cdiv(NP, 4), 256>>>(xp, off_c,   adj_c,   m0,  NP);
    gather_mean_kernel<<<cdiv(NP, 4), 256>>>(tA, off_w,   adj_w,   gg1, NP);
    gather_mean_kernel<<<cdiv(NP, 4), 256>>>(tF, off_rt,  adj_rt,  gg6, NP);
    gather_mean_kernel<<<cdiv(NA, 4), 256>>>(xp, off_rw,  adj_rw,  ma2, NA);
    gather_mean_kernel<<<cdiv(NA, 4), 256>>>(tI, off_raf, adj_raf, gg4, NA);
    gather_mean_kernel<<<cdiv(NF, 4), 256>>>(xp, off_t,   adj_t,   mf5, NF);

    // p1 = relu(m0@Wl0 + xp@WrP0 + bP0 + gg1 + gg6)
    launch_gemm(NP, HD, 2, m0, Wl0 + 0 * WSZ, xp, WrP, 2, gg1, gg6, bP, p1, 1);
    // a1 = relu(ma2@Wl2 + xa@WrA0 + bA0 + gg4)
    launch_gemm(NA, HD, 2, ma2, Wl0 + 2 * WSZ, xa, WrA, 1, gg4, 0, bA, a1, 1);
    // f1 = relu(mf5@Wl5 + xf@Wr5 + bl5)
    launch_gemm(NF, HD, 2, mf5, Wl0 + 5 * WSZ, xf, Wr + 5 * WSZ,
                0, 0, 0, bl0 + 5 * HD, f1, 1);

    // ================= LAYER 2 (paper only — a/i/f outputs are dead) =================
    launch_gemm(NA, HD, 1, a1, Wl1 + 1 * WSZ, 0, 0, 0, 0, 0, 0, tA, 0);
    launch_gemm(NF, HD, 1, f1, Wl1 + 6 * WSZ, 0, 0, 0, 0, 0, 0, tF, 0);

    gather_mean_kernel<<<cdiv(NP, 4), 256>>>(p1, off_c,  adj_c,  m0,  NP);
    gather_mean_kernel<<<cdiv(NP, 4), 256>>>(tA, off_w,  adj_w,  gg1, NP);
    gather_mean_kernel<<<cdiv(NP, 4), 256>>>(tF, off_rt, adj_rt, gg6, NP);

    // p2 = relu(m0@Wl0(l1) + p1@WrP1 + bP1 + gg1 + gg6)
    launch_gemm(NP, HD, 2, m0, Wl1 + 0 * WSZ, p1, WrP + WSZ,
                2, gg1, gg6, bP + HD, p2, 1);

    // ---- final projection: out = p2 @ W_out + b_out ----
    launch_gemm(NP, NOUT, 1, p2, Wout, 0, 0, 0, 0, 0, bout, (float*)d_out, 0);
}

// round 16
// speedup vs baseline: 1.3169x; 1.0642x over previous
#include <cuda_runtime.h>
#include <cstdint>

#define NP 200000
#define NA 100000
#define NI 8000
#define NF 30000
#define HD 256
#define NOUT 349
#define E_C 500000
#define E_W 400000
#define E_A 100000
#define E_T 300000

// ---------------- scratch (static device allocations, allowed) ----------------
__device__ float g_mp0[(size_t)NP * HD];   // m0: mean cites(p) raw
__device__ float g_mp1[(size_t)NP * HD];   // g1: mean writes(a@Wl1)
__device__ float g_mp6[(size_t)NP * HD];   // g6: mean rev_topic(f@Wl6)
__device__ float g_ma2[(size_t)NA * HD];   // ma2: mean rev_writes(p) raw
__device__ float g_ma4[(size_t)NA * HD];   // g4: mean rev_aff(i@Wl4)
__device__ float g_mf5[(size_t)NF * HD];   // mf5: mean topic(p) raw

__device__ float g_tA[(size_t)NA * HD];    // a @ Wl1
__device__ float g_tI[(size_t)NI * HD];    // i @ Wl4
__device__ float g_tF[(size_t)NF * HD];    // f @ Wl6

__device__ float g_p1[(size_t)NP * HD];    // layer-1 paper
__device__ float g_p2[(size_t)NP * HD];    // layer-2 paper
__device__ float g_a1[(size_t)NA * HD];    // layer-1 author
__device__ float g_f1[(size_t)NF * HD];    // layer-1 fos

__device__ float g_WrP[2 * HD * HD];       // combined Wr for paper (r0+r1+r6), per layer
__device__ float g_WrA[2 * HD * HD];       // combined Wr for author (r2+r4)
__device__ float g_bP[2 * HD];
__device__ float g_bA[2 * HD];

// CSR scratch: cnt doubles as cursor after scan
__device__ int g_cnt_c[NP];   __device__ int g_off_c[NP + 1];   __device__ int g_adj_c[E_C];
__device__ int g_cnt_w[NP];   __device__ int g_off_w[NP + 1];   __device__ int g_adj_w[E_W];
__device__ int g_cnt_rw[NA];  __device__ int g_off_rw[NA + 1];  __device__ int g_adj_rw[E_W];
__device__ int g_cnt_raf[NA]; __device__ int g_off_raf[NA + 1]; __device__ int g_adj_raf[E_A];
__device__ int g_cnt_t[NF];   __device__ int g_off_t[NF + 1];   __device__ int g_adj_t[E_T];
__device__ int g_cnt_rt[NP];  __device__ int g_off_rt[NP + 1];  __device__ int g_adj_rt[E_T];

// ---------------- small kernels ----------------
__global__ void hist_kernel(const int* __restrict__ dst, int E, int* cnt) {
    int i = blockIdx.x * blockDim.x + threadIdx.x;
    if (i < E) atomicAdd(&cnt[dst[i]], 1);
}

__global__ void scan_kernel(int* cnt, int n, int* offs) {
    __shared__ int sh[1024];
    int tid = threadIdx.x;
    int chunk = (n + 1023) >> 10;
    int beg = tid * chunk;
    int end = beg + chunk; if (end > n) end = n;
    int s = 0;
    for (int i = beg; i < end; i++) s += cnt[i];
    sh[tid] = s;
    __syncthreads();
    for (int d = 1; d < 1024; d <<= 1) {
        int t = (tid >= d) ? sh[tid - d] : 0;
        __syncthreads();
        sh[tid] += t;
        __syncthreads();
    }
    int run = sh[tid] - s;
    for (int i = beg; i < end; i++) {
        int c = cnt[i];
        offs[i] = run;
        cnt[i]  = run;
        run += c;
    }
    if (beg < n && end == n) offs[n] = run;
}

__global__ void fill_kernel(const int* __restrict__ src, const int* __restrict__ dst,
                            int E, int* cursor, int* __restrict__ adj) {
    int i = blockIdx.x * blockDim.x + threadIdx.x;
    if (i < E) {
        int p = atomicAdd(&cursor[dst[i]], 1);
        adj[p] = src[i];
    }
}

// mean aggregation: 64 threads per dst node (float4 per thread), 4 nodes per block
__global__ void gather_mean_kernel(const float* __restrict__ x,
                                   const int* __restrict__ offs,
                                   const int* __restrict__ adj,
                                   float* __restrict__ out, int n_dst) {
    int node = blockIdx.x * 4 + (threadIdx.x >> 6);
    int lane = threadIdx.x & 63;
    if (node >= n_dst) return;
    int beg = offs[node], end = offs[node + 1];
    float4 acc = make_float4(0.f, 0.f, 0.f, 0.f);
    int e = beg;
    for (; e + 1 < end; e += 2) {
        int s0 = adj[e], s1 = adj[e + 1];
        float4 v0 = ((const float4*)(x + (size_t)s0 * HD))[lane];
        float4 v1 = ((const float4*)(x + (size_t)s1 * HD))[lane];
        acc.x += v0.x + v1.x; acc.y += v0.y + v1.y;
        acc.z += v0.z + v1.z; acc.w += v0.w + v1.w;
    }
    if (e < end) {
        float4 v = ((const float4*)(x + (size_t)adj[e] * HD))[lane];
        acc.x += v.x; acc.y += v.y; acc.z += v.z; acc.w += v.w;
    }
    float inv = (end > beg) ? 1.f / (float)(end - beg) : 0.f;
    float4 r = make_float4(acc.x * inv, acc.y * inv, acc.z * inv, acc.w * inv);
    ((float4*)(out + (size_t)node * HD))[lane] = r;
}

__global__ void combine_kernel(const float* __restrict__ Wr, const float* __restrict__ bl,
                               float* __restrict__ WrP, float* __restrict__ WrA,
                               float* __restrict__ bP, float* __restrict__ bA) {
    int idx = blockIdx.x * blockDim.x + threadIdx.x;
    if (idx < 2 * HD * HD) {
        int l = idx / (HD * HD), j = idx % (HD * HD);
        const float* base = Wr + (size_t)l * 7 * HD * HD;
        WrP[idx] = base[0 * HD * HD + j] + base[1 * HD * HD + j] + base[6 * HD * HD + j];
        WrA[idx] = base[2 * HD * HD + j] + base[4 * HD * HD + j];
    }
    if (idx < 2 * HD) {
        int l = idx / HD, j = idx % HD;
        const float* bb = bl + (size_t)l * 7 * HD;
        bP[idx] = bb[0 * HD + j] + bb[1 * HD + j] + bb[6 * HD + j];
        bA[idx] = bb[2 * HD + j] + bb[4 * HD + j];
    }
}

// ---------------- tf32 tensor-core multi-part GEMM (R13 proven) ----------------
// C[M,N] = act( sum_p A_p[M,256] @ W_p[256,N] + bias + add0 + add1 )
// A stored in smem in MMA-fragment order -> one LDS.128 per A fragment.
struct GemmArgs {
    const float* A[2];
    const float* W[2];
    const float* add0; const float* add1;
    const float* bias;
    float* C;
    int nparts, nadd, M, N, relu;
};

__device__ __forceinline__ float to_tf32(float x) {
    uint32_t u;
    asm("cvt.rna.tf32.f32 %0, %1;" : "=r"(u) : "f"(x));
    return __uint_as_float(u);
}

__device__ __forceinline__ void mma_tf32(float* c, const uint32_t* a, const uint32_t* b) {
    asm volatile(
        "mma.sync.aligned.m16n8k8.row.col.f32.tf32.tf32.f32 "
        "{%0,%1,%2,%3}, {%4,%5,%6,%7}, {%8,%9}, {%0,%1,%2,%3};\n"
        : "+f"(c[0]), "+f"(c[1]), "+f"(c[2]), "+f"(c[3])
        : "r"(a[0]), "r"(a[1]), "r"(a[2]), "r"(a[3]), "r"(b[0]), "r"(b[1]));
}

#define BK 32
#define APITCH 136  // B pitch: fragment scalar loads conflict-free

__global__ __launch_bounds__(256) void gemm_tf32_kernel(GemmArgs g) {
    __shared__ float Af[4096];        // A fragments, 16 KB
    __shared__ float Bs[BK][APITCH];  // k-major: Bs[k][n]

    int tid = threadIdx.x;
    int bm = blockIdx.y * 128;
    int bn = blockIdx.x * 128;
    int warp = tid >> 5, lane = tid & 31;
    int warp_m = warp >> 2;          // 0..1  -> 64 rows each
    int warp_n = warp & 3;           // 0..3  -> 32 cols each
    int gq = lane >> 2, tig = lane & 3;
    int ulsw = (lane ^ (lane >> 3)) * 4;   // consumer unit-swizzled float offset

    int lm = tid & 127;
    int lk = tid >> 7;               // 0/1
    bool arow_ok = (bm + lm) < g.M;
    int wml = lm >> 6;
    int il  = (lm >> 4) & 3;
    int gql = lm & 7;
    int rb0 = (lm >> 3) & 1;
    int rsw = (il & 1) << 1;

    int nc = (tid & 31) * 4;
    int kr = tid >> 5;               // 0..7

    float acc[4][4][4];
#pragma unroll
    for (int i = 0; i < 4; i++)
#pragma unroll
        for (int j = 0; j < 4; j++)
#pragma unroll
            for (int q = 0; q < 4; q++) acc[i][j][q] = 0.f;

    for (int p = 0; p < g.nparts; p++) {
        const float* A = g.A[p];
        const float* W = g.W[p];
        for (int k0 = 0; k0 < HD; k0 += BK) {
            const float* Arow = A + (size_t)(bm + lm) * HD + k0 + lk * 16;
#pragma unroll
            for (int ii = 0; ii < 4; ii++) {
                float4 v = make_float4(0.f, 0.f, 0.f, 0.f);
                if (arow_ok) v = *(const float4*)(Arow + ii * 4);
                float vv[4] = { v.x, v.y, v.z, v.w };
#pragma unroll
                for (int cc = 0; cc < 4; cc++) {
                    int kk = lk * 16 + ii * 4 + cc;
                    int ks = kk >> 3;
                    int tg = kk & 3;
                    int rb1 = (kk >> 2) & 1;
                    int r  = rb0 | (rb1 << 1);
                    int rp = r ^ rsw;
                    int u  = gql * 4 + tg;
                    int up = u ^ (u >> 3);
                    Af[(((ks * 2 + wml) * 4 + il) << 7) + up * 4 + rp] = to_tf32(vv[cc]);
                }
            }
#pragma unroll
            for (int i = 0; i < 4; i++) {
                int krow = kr + i * 8;
                const float* Wp = W + (size_t)(k0 + krow) * g.N + bn + nc;
                float4 v;
                v.x = (bn + nc + 0 < g.N) ? Wp[0] : 0.f;
                v.y = (bn + nc + 1 < g.N) ? Wp[1] : 0.f;
                v.z = (bn + nc + 2 < g.N) ? Wp[2] : 0.f;
                v.w = (bn + nc + 3 < g.N) ? Wp[3] : 0.f;
                v.x = to_tf32(v.x); v.y = to_tf32(v.y);
                v.z = to_tf32(v.z); v.w = to_tf32(v.w);
                *(float4*)(&Bs[krow][nc]) = v;
            }
            __syncthreads();

#pragma unroll
            for (int ks = 0; ks < 4; ks++) {
                int kb = ks * 8;
                uint32_t afr[4][4];
#pragma unroll
                for (int i = 0; i < 4; i++) {
                    const float4 av = *(const float4*)(
                        Af + (((ks * 2 + warp_m) * 4 + i) << 7) + ulsw);
                    if ((i & 1) == 0) {
                        afr[i][0] = __float_as_uint(av.x);
                        afr[i][1] = __float_as_uint(av.y);
                        afr[i][2] = __float_as_uint(av.z);
                        afr[i][3] = __float_as_uint(av.w);
                    } else {
                        afr[i][0] = __float_as_uint(av.z);
                        afr[i][1] = __float_as_uint(av.w);
                        afr[i][2] = __float_as_uint(av.x);
                        afr[i][3] = __float_as_uint(av.y);
                    }
                }
                uint32_t bfr[4][2];
#pragma unroll
                for (int j = 0; j < 4; j++) {
                    int nb = warp_n * 32 + j * 8;
                    bfr[j][0] = __float_as_uint(Bs[kb + tig][nb + gq]);
                    bfr[j][1] = __float_as_uint(Bs[kb + tig + 4][nb + gq]);
                }
#pragma unroll
                for (int i = 0; i < 4; i++)
#pragma unroll
                    for (int j = 0; j < 4; j++)
                        mma_tf32(acc[i][j], afr[i], bfr[j]);
            }
            __syncthreads();
        }
    }

    // ---- epilogue: addends + bias + relu + guarded store ----
#pragma unroll
    for (int i = 0; i < 4; i++) {
        int r0 = bm + warp_m * 64 + i * 16 + gq;
        int r1 = r0 + 8;
#pragma unroll
        for (int j = 0; j < 4; j++) {
            int c0 = bn + warp_n * 32 + j * 8 + tig * 2;
            bool c0ok = c0 < g.N, c1ok = (c0 + 1) < g.N;
            float bia0 = 0.f, bia1 = 0.f;
            if (g.bias) {
                if (c0ok) bia0 = g.bias[c0];
                if (c1ok) bia1 = g.bias[c0 + 1];
            }
            float v00 = acc[i][j][0] + bia0, v01 = acc[i][j][1] + bia1;
            float v10 = acc[i][j][2] + bia0, v11 = acc[i][j][3] + bia1;
            if (g.nadd > 0) {
                const float* a0p = g.add0;
                if (r0 < g.M) {
                    if (c0ok) v00 += a0p[(size_t)r0 * g.N + c0];
                    if (c1ok) v01 += a0p[(size_t)r0 * g.N + c0 + 1];
                }
                if (r1 < g.M) {
                    if (c0ok) v10 += a0p[(size_t)r1 * g.N + c0];
                    if (c1ok) v11 += a0p[(size_t)r1 * g.N + c0 + 1];
                }
            }
            if (g.nadd > 1) {
                const float* a1p = g.add1;
                if (r0 < g.M) {
                    if (c0ok) v00 += a1p[(size_t)r0 * g.N + c0];
                    if (c1ok) v01 += a1p[(size_t)r0 * g.N + c0 + 1];
                }
                if (r1 < g.M) {
                    if (c0ok) v10 += a1p[(size_t)r1 * g.N + c0];
                    if (c1ok) v11 += a1p[(size_t)r1 * g.N + c0 + 1];
                }
            }
            if (g.relu) {
                v00 = v00 > 0.f ? v00 : 0.f; v01 = v01 > 0.f ? v01 : 0.f;
                v10 = v10 > 0.f ? v10 : 0.f; v11 = v11 > 0.f ? v11 : 0.f;
            }
            if (r0 < g.M) {
                if (c0ok) g.C[(size_t)r0 * g.N + c0]     = v00;
                if (c1ok) g.C[(size_t)r0 * g.N + c0 + 1] = v01;
            }
            if (r1 < g.M) {
                if (c0ok) g.C[(size_t)r1 * g.N + c0]     = v10;
                if (c1ok) g.C[(size_t)r1 * g.N + c0 + 1] = v11;
            }
        }
    }
}

// ---------------- host ----------------
static inline int cdiv(int a, int b) { return (a + b - 1) / b; }

static void launch_gemm(cudaStream_t st, int M, int N, int nparts,
                        const float* A0, const float* W0,
                        const float* A1, const float* W1,
                        int nadd, const float* add0, const float* add1,
                        const float* bias, float* C, int relu) {
    GemmArgs g;
    g.A[0] = A0; g.A[1] = A1; g.W[0] = W0; g.W[1] = W1;
    g.add0 = add0; g.add1 = add1;
    g.nparts = nparts; g.nadd = nadd; g.M = M; g.N = N;
    g.bias = bias; g.C = C; g.relu = relu;
    dim3 grid(cdiv(N, 128), cdiv(M, 128));
    gemm_tf32_kernel<<<grid, 256, 0, st>>>(g);
}

extern "C" void kernel_launch(void* const* d_in, const int* in_sizes, int n_in,
                              void* d_out, int out_size) {
    const float* xp = (const float*)d_in[0];
    const float* xa = (const float*)d_in[1];
    const float* xi = (const float*)d_in[2];
    const float* xf = (const float*)d_in[3];
    const int* cites_src = (const int*)d_in[4];
    const int* cites_dst = (const int*)d_in[5];
    const int* writes_src = (const int*)d_in[6];
    const int* writes_dst = (const int*)d_in[7];
    const int* rwrites_src = (const int*)d_in[8];
    const int* rwrites_dst = (const int*)d_in[9];
    const int* raff_src = (const int*)d_in[12];
    const int* raff_dst = (const int*)d_in[13];
    const int* topic_src = (const int*)d_in[14];
    const int* topic_dst = (const int*)d_in[15];
    const int* rtopic_src = (const int*)d_in[16];
    const int* rtopic_dst = (const int*)d_in[17];
    const float* Wl = (const float*)d_in[18];
    const float* bl = (const float*)d_in[19];
    const float* Wr = (const float*)d_in[20];
    const float* Wout = (const float*)d_in[21];
    const float* bout = (const float*)d_in[22];

    // streams/events: created once (host-side resources, no device allocation;
    // must exist BEFORE graph capture, which is satisfied since the correctness
    // call precedes the capture call). Work per call is identical every call.
    static cudaStream_t sMem = 0;
    static cudaEvent_t ev[7];
    if (!sMem) {
        cudaStreamCreateWithFlags(&sMem, cudaStreamNonBlocking);
        for (int i = 0; i < 7; i++)
            cudaEventCreateWithFlags(&ev[i], cudaEventDisableTiming);
    }
    cudaStream_t s0 = 0;  // compute stream (the captured/legacy stream)

    float *m0, *gg1, *gg6, *ma2, *gg4, *mf5, *tA, *tI, *tF;
    float *p1, *p2, *a1, *f1, *WrP, *WrA, *bP, *bA;
    int *cnt_c, *off_c, *adj_c, *cnt_w, *off_w, *adj_w;
    int *cnt_rw, *off_rw, *adj_rw;
    int *cnt_raf, *off_raf, *adj_raf, *cnt_t, *off_t, *adj_t;
    int *cnt_rt, *off_rt, *adj_rt;
    cudaGetSymbolAddress((void**)&m0, g_mp0);
    cudaGetSymbolAddress((void**)&gg1, g_mp1);
    cudaGetSymbolAddress((void**)&gg6, g_mp6);
    cudaGetSymbolAddress((void**)&ma2, g_ma2);
    cudaGetSymbolAddress((void**)&gg4, g_ma4);
    cudaGetSymbolAddress((void**)&mf5, g_mf5);
    cudaGetSymbolAddress((void**)&tA, g_tA);
    cudaGetSymbolAddress((void**)&tI, g_tI);
    cudaGetSymbolAddress((void**)&tF, g_tF);
    cudaGetSymbolAddress((void**)&p1, g_p1);
    cudaGetSymbolAddress((void**)&p2, g_p2);
    cudaGetSymbolAddress((void**)&a1, g_a1);
    cudaGetSymbolAddress((void**)&f1, g_f1);
    cudaGetSymbolAddress((void**)&WrP, g_WrP);
    cudaGetSymbolAddress((void**)&WrA, g_WrA);
    cudaGetSymbolAddress((void**)&bP, g_bP);
    cudaGetSymbolAddress((void**)&bA, g_bA);
    cudaGetSymbolAddress((void**)&cnt_c, g_cnt_c);
    cudaGetSymbolAddress((void**)&off_c, g_off_c);
    cudaGetSymbolAddress((void**)&adj_c, g_adj_c);
    cudaGetSymbolAddress((void**)&cnt_w, g_cnt_w);
    cudaGetSymbolAddress((void**)&off_w, g_off_w);
    cudaGetSymbolAddress((void**)&adj_w, g_adj_w);
    cudaGetSymbolAddress((void**)&cnt_rw, g_cnt_rw);
    cudaGetSymbolAddress((void**)&off_rw, g_off_rw);
    cudaGetSymbolAddress((void**)&adj_rw, g_adj_rw);
    cudaGetSymbolAddress((void**)&cnt_raf, g_cnt_raf);
    cudaGetSymbolAddress((void**)&off_raf, g_off_raf);
    cudaGetSymbolAddress((void**)&adj_raf, g_adj_raf);
    cudaGetSymbolAddress((void**)&cnt_t, g_cnt_t);
    cudaGetSymbolAddress((void**)&off_t, g_off_t);
    cudaGetSymbolAddress((void**)&adj_t, g_adj_t);
    cudaGetSymbolAddress((void**)&cnt_rt, g_cnt_rt);
    cudaGetSymbolAddress((void**)&off_rt, g_off_rt);
    cudaGetSymbolAddress((void**)&adj_rt, g_adj_rt);

    const size_t WSZ = (size_t)HD * HD;
    const float* Wl0 = Wl;                     const float* bl0 = bl;
    const float* Wl1 = Wl + 7 * WSZ;

    // ---- fork memory stream off the capture stream ----
    cudaEventRecord(ev[0], s0);
    cudaStreamWaitEvent(sMem, ev[0], 0);

    // ---- memory stream: CSR builds for the 6 live relations ----
    struct Rel { const int* src; const int* dst; int E; int n_dst; int* cnt; int* off; int* adj; };
    Rel rels[6] = {
        { cites_src,   cites_dst,   E_C, NP, cnt_c,   off_c,   adj_c   },
        { writes_src,  writes_dst,  E_W, NP, cnt_w,   off_w,   adj_w   },
        { rtopic_src,  rtopic_dst,  E_T, NP, cnt_rt,  off_rt,  adj_rt  },
        { rwrites_src, rwrites_dst, E_W, NA, cnt_rw,  off_rw,  adj_rw  },
        { raff_src,    raff_dst,    E_A, NA, cnt_raf, off_raf, adj_raf },
        { topic_src,   topic_dst,   E_T, NF, cnt_t,   off_t,   adj_t   },
    };
    for (int r = 0; r < 6; r++) {
        cudaMemsetAsync(rels[r].cnt, 0, (size_t)rels[r].n_dst * sizeof(int), sMem);
        hist_kernel<<<cdiv(rels[r].E, 256), 256, 0, sMem>>>(rels[r].dst, rels[r].E, rels[r].cnt);
        scan_kernel<<<1, 1024, 0, sMem>>>(rels[r].cnt, rels[r].n_dst, rels[r].off);
        fill_kernel<<<cdiv(rels[r].E, 256), 256, 0, sMem>>>(rels[r].src, rels[r].dst, rels[r].E,
                                                            rels[r].cnt, rels[r].adj);
    }

    // ---- compute stream: combine + L1 src-side transforms (concurrent w/ CSR) ----
    combine_kernel<<<cdiv(2 * HD * HD, 256), 256, 0, s0>>>(Wr, bl, WrP, WrA, bP, bA);
    launch_gemm(s0, NA, HD, 1, xa, Wl0 + 1 * WSZ, 0, 0, 0, 0, 0, 0, tA, 0);
    launch_gemm(s0, NF, HD, 1, xf, Wl0 + 6 * WSZ, 0, 0, 0, 0, 0, 0, tF, 0);
    launch_gemm(s0, NI, HD, 1, xi, Wl0 + 4 * WSZ, 0, 0, 0, 0, 0, 0, tI, 0);
    cudaEventRecord(ev[1], s0);                 // transforms done

    // ---- memory stream: L1 gathers ----
    gather_mean_kernel<<<cdiv(NP, 4), 256, 0, sMem>>>(xp, off_c, adj_c, m0, NP);
    cudaStreamWaitEvent(sMem, ev[1], 0);        // tA/tF/tI ready
    gather_mean_kernel<<<cdiv(NP, 4), 256, 0, sMem>>>(tA, off_w,  adj_w,  gg1, NP);
    gather_mean_kernel<<<cdiv(NP, 4), 256, 0, sMem>>>(tF, off_rt, adj_rt, gg6, NP);
    cudaEventRecord(ev[2], sMem);               // p1's gather inputs ready
    gather_mean_kernel<<<cdiv(NA, 4), 256, 0, sMem>>>(xp, off_rw,  adj_rw,  ma2, NA);
    gather_mean_kernel<<<cdiv(NA, 4), 256, 0, sMem>>>(tI, off_raf, adj_raf, gg4, NA);
    gather_mean_kernel<<<cdiv(NF, 4), 256, 0, sMem>>>(xp, off_t,   adj_t,   mf5, NF);
    cudaEventRecord(ev[3], sMem);               // a1/f1 gather inputs ready

    // ---- compute: p1 (overlaps ma2/gg4/mf5 gathers on sMem) ----
    cudaStreamWaitEvent(s0, ev[2], 0);
    launch_gemm(s0, NP, HD, 2, m0, Wl0 + 0 * WSZ, xp, WrP, 2, gg1, gg6, bP, p1, 1);
    cudaEventRecord(ev[4], s0);                 // p1 done (also: m0/gg1/gg6 free)

    // ---- memory: L2 cites gather on p1 (overlaps a1/f1/tA2/tF2 on s0) ----
    cudaStreamWaitEvent(sMem, ev[4], 0);
    gather_mean_kernel<<<cdiv(NP, 4), 256, 0, sMem>>>(p1, off_c, adj_c, m0, NP);

    // ---- compute: a1, tA2, f1, tF2 ----
    cudaStreamWaitEvent(s0, ev[3], 0);
    launch_gemm(s0, NA, HD, 2, ma2, Wl0 + 2 * WSZ, xa, WrA, 1, gg4, 0, bA, a1, 1);
    launch_gemm(s0, NA, HD, 1, a1, Wl1 + 1 * WSZ, 0, 0, 0, 0, 0, 0, tA, 0);
    cudaEventRecord(ev[5], s0);                 // tA2 ready
    launch_gemm(s0, NF, HD, 2, mf5, Wl0 + 5 * WSZ, xf, Wr + 5 * WSZ,
                0, 0, 0, bl0 + 5 * HD, f1, 1);
    launch_gemm(s0, NF, HD, 1, f1, Wl1 + 6 * WSZ, 0, 0, 0, 0, 0, 0, tF, 0);
    cudaEventRecord(ev[6], s0);                 // tF2 ready

    // ---- memory: L2 writes/rev_topic gathers ----
    cudaStreamWaitEvent(sMem, ev[5], 0);
    gather_mean_kernel<<<cdiv(NP, 4), 256, 0, sMem>>>(tA, off_w,  adj_w,  gg1, NP);
    cudaStreamWaitEvent(sMem, ev[6], 0);
    gather_mean_kernel<<<cdiv(NP, 4), 256, 0, sMem>>>(tF, off_rt, adj_rt, gg6, NP);
    cudaEventRecord(ev[0], sMem);               // all L2 gathers done (join)

    // ---- compute: p2 + output projection (rejoined: sMem fully merged) ----
    cudaStreamWaitEvent(s0, ev[0], 0);
    launch_gemm(s0, NP, HD, 2, m0, Wl1 + 0 * WSZ, p1, WrP + WSZ,
                2, gg1, gg6, bP + HD, p2, 1);
    launch_gemm(s0, NP, NOUT, 1, p2, Wout, 0, 0, 0, 0, 0, bout, (float*)d_out, 0);
}

// round 17
// speedup vs baseline: 1.4849x; 1.1276x over previous
#include <cuda_runtime.h>
#include <cuda_fp16.h>
#include <cstdint>

#define NP 200000
#define NA 100000
#define NI 8000
#define NF 30000
#define HD 256
#define NOUT 349
#define E_C 500000
#define E_W 400000
#define E_A 100000
#define E_T 300000

// ---------------- scratch (static device allocations, allowed) ----------------
__device__ float g_mp0[(size_t)NP * HD];   // m0: mean cites(p) raw
__device__ float g_mp1[(size_t)NP * HD];   // g1: mean writes(a@Wl1)
__device__ float g_mp6[(size_t)NP * HD];   // g6: mean rev_topic(f@Wl6)
__device__ float g_ma2[(size_t)NA * HD];   // ma2: mean rev_writes(p) raw
__device__ float g_ma4[(size_t)NA * HD];   // g4: mean rev_aff(i@Wl4)
__device__ float g_mf5[(size_t)NF * HD];   // mf5: mean topic(p) raw

__device__ float g_tA[(size_t)NA * HD];    // a @ Wl1
__device__ float g_tI[(size_t)NI * HD];    // i @ Wl4
__device__ float g_tF[(size_t)NF * HD];    // f @ Wl6

__device__ float g_p1[(size_t)NP * HD];    // layer-1 paper
__device__ float g_p2[(size_t)NP * HD];    // layer-2 paper
__device__ float g_a1[(size_t)NA * HD];    // layer-1 author
__device__ float g_f1[(size_t)NF * HD];    // layer-1 fos

__device__ float g_WrP[2 * HD * HD];       // combined Wr for paper (r0+r1+r6), per layer
__device__ float g_WrA[2 * HD * HD];       // combined Wr for author (r2+r4)
__device__ float g_bP[2 * HD];
__device__ float g_bA[2 * HD];

// CSR scratch: cnt doubles as cursor after scan
__device__ int g_cnt_c[NP];   __device__ int g_off_c[NP + 1];   __device__ int g_adj_c[E_C];
__device__ int g_cnt_w[NP];   __device__ int g_off_w[NP + 1];   __device__ int g_adj_w[E_W];
__device__ int g_cnt_rw[NA];  __device__ int g_off_rw[NA + 1];  __device__ int g_adj_rw[E_W];
__device__ int g_cnt_raf[NA]; __device__ int g_off_raf[NA + 1]; __device__ int g_adj_raf[E_A];
__device__ int g_cnt_t[NF];   __device__ int g_off_t[NF + 1];   __device__ int g_adj_t[E_T];
__device__ int g_cnt_rt[NP];  __device__ int g_off_rt[NP + 1];  __device__ int g_adj_rt[E_T];

// ---------------- small kernels ----------------
__global__ void hist_kernel(const int* __restrict__ dst, int E, int* cnt) {
    int i = blockIdx.x * blockDim.x + threadIdx.x;
    if (i < E) atomicAdd(&cnt[dst[i]], 1);
}

__global__ void scan_kernel(int* cnt, int n, int* offs) {
    __shared__ int sh[1024];
    int tid = threadIdx.x;
    int chunk = (n + 1023) >> 10;
    int beg = tid * chunk;
    int end = beg + chunk; if (end > n) end = n;
    int s = 0;
    for (int i = beg; i < end; i++) s += cnt[i];
    sh[tid] = s;
    __syncthreads();
    for (int d = 1; d < 1024; d <<= 1) {
        int t = (tid >= d) ? sh[tid - d] : 0;
        __syncthreads();
        sh[tid] += t;
        __syncthreads();
    }
    int run = sh[tid] - s;
    for (int i = beg; i < end; i++) {
        int c = cnt[i];
        offs[i] = run;
        cnt[i]  = run;
        run += c;
    }
    if (beg < n && end == n) offs[n] = run;
}

__global__ void fill_kernel(const int* __restrict__ src, const int* __restrict__ dst,
                            int E, int* cursor, int* __restrict__ adj) {
    int i = blockIdx.x * blockDim.x + threadIdx.x;
    if (i < E) {
        int p = atomicAdd(&cursor[dst[i]], 1);
        adj[p] = src[i];
    }
}

// mean aggregation: 64 threads per dst node (float4 per thread), 4 nodes per block
__global__ void gather_mean_kernel(const float* __restrict__ x,
                                   const int* __restrict__ offs,
                                   const int* __restrict__ adj,
                                   float* __restrict__ out, int n_dst) {
    int node = blockIdx.x * 4 + (threadIdx.x >> 6);
    int lane = threadIdx.x & 63;
    if (node >= n_dst) return;
    int beg = offs[node], end = offs[node + 1];
    float4 acc = make_float4(0.f, 0.f, 0.f, 0.f);
    int e = beg;
    for (; e + 1 < end; e += 2) {
        int s0 = adj[e], s1 = adj[e + 1];
        float4 v0 = ((const float4*)(x + (size_t)s0 * HD))[lane];
        float4 v1 = ((const float4*)(x + (size_t)s1 * HD))[lane];
        acc.x += v0.x + v1.x; acc.y += v0.y + v1.y;
        acc.z += v0.z + v1.z; acc.w += v0.w + v1.w;
    }
    if (e < end) {
        float4 v = ((const float4*)(x + (size_t)adj[e] * HD))[lane];
        acc.x += v.x; acc.y += v.y; acc.z += v.z; acc.w += v.w;
    }
    float inv = (end > beg) ? 1.f / (float)(end - beg) : 0.f;
    float4 r = make_float4(acc.x * inv, acc.y * inv, acc.z * inv, acc.w * inv);
    ((float4*)(out + (size_t)node * HD))[lane] = r;
}

__global__ void combine_kernel(const float* __restrict__ Wr, const float* __restrict__ bl,
                               float* __restrict__ WrP, float* __restrict__ WrA,
                               float* __restrict__ bP, float* __restrict__ bA) {
    int idx = blockIdx.x * blockDim.x + threadIdx.x;
    if (idx < 2 * HD * HD) {
        int l = idx / (HD * HD), j = idx % (HD * HD);
        const float* base = Wr + (size_t)l * 7 * HD * HD;
        WrP[idx] = base[0 * HD * HD + j] + base[1 * HD * HD + j] + base[6 * HD * HD + j];
        WrA[idx] = base[2 * HD * HD + j] + base[4 * HD * HD + j];
    }
    if (idx < 2 * HD) {
        int l = idx / HD, j = idx % HD;
        const float* bb = bl + (size_t)l * 7 * HD;
        bP[idx] = bb[0 * HD + j] + bb[1 * HD + j] + bb[6 * HD + j];
        bA[idx] = bb[2 * HD + j] + bb[4 * HD + j];
    }
}

// ---------------- fp16 tensor-core multi-part GEMM -----------------------------
// C[M,N] = act( sum_p A_p[M,256] @ W_p[256,N] + bias + add0 + add1 )
// fp16 inputs (same 11-bit mantissa as tf32), fp32 accumulate, 2x HMMA rate.
struct GemmArgs {
    const float* A[2];
    const float* W[2];
    const float* add0; const float* add1;
    const float* bias;
    float* C;
    int nparts, nadd, M, N, relu;
};

__device__ __forceinline__ void mma_fp16(float* c, const uint32_t* a, const uint32_t* b) {
    asm volatile(
        "mma.sync.aligned.m16n8k16.row.col.f32.f16.f16.f32 "
        "{%0,%1,%2,%3}, {%4,%5,%6,%7}, {%8,%9}, {%0,%1,%2,%3};\n"
        : "+f"(c[0]), "+f"(c[1]), "+f"(c[2]), "+f"(c[3])
        : "r"(a[0]), "r"(a[1]), "r"(a[2]), "r"(a[3]), "r"(b[0]), "r"(b[1]));
}

__device__ __forceinline__ uint32_t h2u(__half2 h) {
    return *reinterpret_cast<uint32_t*>(&h);
}

#define BK 32
#define PA 40    // A smem pitch in halves (80 B/row): ldmatrix phases conflict-free
#define PB 136   // B smem pitch in halves (272 B/row): ldmatrix.trans conflict-free

__global__ __launch_bounds__(256) void gemm_fp16_kernel(GemmArgs g) {
    __shared__ __half As[128 * PA];   // row-major [m][k], 10.2 KB
    __shared__ __half Bs[BK * PB];    // k-major [k][n], 8.7 KB

    int tid = threadIdx.x;
    int bm = blockIdx.y * 128;
    int bn = blockIdx.x * 128;
    int warp = tid >> 5, lane = tid & 31;
    int warp_m = warp >> 2;          // 0..1 -> 64 rows
    int warp_n = warp & 3;           // 0..3 -> 32 cols
    int gq = lane >> 2, tig = lane & 3;

    // A loader: row ar, 16-float half ah of the 32-K chunk
    int ar = tid >> 1, ah = tid & 1;
    bool arow_ok = (bm + ar) < g.M;

    // B loader: 4 cols at nc, k rows kr+{0,8,16,24}
    int nc = (tid & 31) * 4;
    int kr = tid >> 5;

    // ldmatrix lane->row mapping
    int lrow  = ((lane >> 3) & 1) * 8 + (lane & 7);   // A x4: all 32 lanes
    int lkoff = (lane >> 4) * 8;
    int bkrow = lane & 15;                            // B x2: lanes 0-15 used

    uint32_t aBase = (uint32_t)__cvta_generic_to_shared(As);
    uint32_t bBase = (uint32_t)__cvta_generic_to_shared(Bs);

    float acc[4][4][4];
#pragma unroll
    for (int i = 0; i < 4; i++)
#pragma unroll
        for (int j = 0; j < 4; j++)
#pragma unroll
            for (int q = 0; q < 4; q++) acc[i][j][q] = 0.f;

    for (int p = 0; p < g.nparts; p++) {
        const float* A = g.A[p];
        const float* W = g.W[p];
        for (int k0 = 0; k0 < HD; k0 += BK) {
            // ---- load A tile: 16 floats -> 16 fp16, two 16B stores ----
            const float* Arow = A + (size_t)(bm + ar) * HD + k0 + ah * 16;
            uint32_t hv[8];
#pragma unroll
            for (int i = 0; i < 4; i++) {
                float4 v = make_float4(0.f, 0.f, 0.f, 0.f);
                if (arow_ok) v = *(const float4*)(Arow + i * 4);
                hv[i * 2 + 0] = h2u(__floats2half2_rn(v.x, v.y));
                hv[i * 2 + 1] = h2u(__floats2half2_rn(v.z, v.w));
            }
            {
                uint4* dst = (uint4*)&As[ar * PA + ah * 16];
                dst[0] = make_uint4(hv[0], hv[1], hv[2], hv[3]);
                dst[1] = make_uint4(hv[4], hv[5], hv[6], hv[7]);
            }
            // ---- load B tile: guarded scalar loads -> fp16, 8B stores ----
#pragma unroll
            for (int i = 0; i < 4; i++) {
                int krow = kr + i * 8;
                const float* Wp = W + (size_t)(k0 + krow) * g.N + bn + nc;
                float x0 = (bn + nc + 0 < g.N) ? Wp[0] : 0.f;
                float x1 = (bn + nc + 1 < g.N) ? Wp[1] : 0.f;
                float x2 = (bn + nc + 2 < g.N) ? Wp[2] : 0.f;
                float x3 = (bn + nc + 3 < g.N) ? Wp[3] : 0.f;
                uint2* dst = (uint2*)&Bs[krow * PB + nc];
                *dst = make_uint2(h2u(__floats2half2_rn(x0, x1)),
                                  h2u(__floats2half2_rn(x2, x3)));
            }
            __syncthreads();

            // ---- 2 k16-steps of m16n8k16 fp16 mma ----
#pragma unroll
            for (int ks = 0; ks < 2; ks++) {
                int kb = ks * 16;
                uint32_t afr[4][4];
#pragma unroll
                for (int i = 0; i < 4; i++) {
                    uint32_t addr = aBase +
                        ((warp_m * 64 + i * 16 + lrow) * PA + kb + lkoff) * 2;
                    asm volatile(
                        "ldmatrix.sync.aligned.m8n8.x4.shared.b16 {%0,%1,%2,%3}, [%4];"
                        : "=r"(afr[i][0]), "=r"(afr[i][1]),
                          "=r"(afr[i][2]), "=r"(afr[i][3])
                        : "r"(addr));
                }
                uint32_t bfr[4][2];
#pragma unroll
                for (int j = 0; j < 4; j++) {
                    uint32_t addr = bBase +
                        ((kb + bkrow) * PB + warp_n * 32 + j * 8) * 2;
                    asm volatile(
                        "ldmatrix.sync.aligned.m8n8.x2.trans.shared.b16 {%0,%1}, [%2];"
                        : "=r"(bfr[j][0]), "=r"(bfr[j][1])
                        : "r"(addr));
                }
#pragma unroll
                for (int i = 0; i < 4; i++)
#pragma unroll
                    for (int j = 0; j < 4; j++)
                        mma_fp16(acc[i][j], afr[i], bfr[j]);
            }
            __syncthreads();
        }
    }

    // ---- epilogue: addends + bias + relu + guarded store (same C layout) ----
#pragma unroll
    for (int i = 0; i < 4; i++) {
        int r0 = bm + warp_m * 64 + i * 16 + gq;
        int r1 = r0 + 8;
#pragma unroll
        for (int j = 0; j < 4; j++) {
            int c0 = bn + warp_n * 32 + j * 8 + tig * 2;
            bool c0ok = c0 < g.N, c1ok = (c0 + 1) < g.N;
            float bia0 = 0.f, bia1 = 0.f;
            if (g.bias) {
                if (c0ok) bia0 = g.bias[c0];
                if (c1ok) bia1 = g.bias[c0 + 1];
            }
            float v00 = acc[i][j][0] + bia0, v01 = acc[i][j][1] + bia1;
            float v10 = acc[i][j][2] + bia0, v11 = acc[i][j][3] + bia1;
            if (g.nadd > 0) {
                const float* a0p = g.add0;
                if (r0 < g.M) {
                    if (c0ok) v00 += a0p[(size_t)r0 * g.N + c0];
                    if (c1ok) v01 += a0p[(size_t)r0 * g.N + c0 + 1];
                }
                if (r1 < g.M) {
                    if (c0ok) v10 += a0p[(size_t)r1 * g.N + c0];
                    if (c1ok) v11 += a0p[(size_t)r1 * g.N + c0 + 1];
                }
            }
            if (g.nadd > 1) {
                const float* a1p = g.add1;
                if (r0 < g.M) {
                    if (c0ok) v00 += a1p[(size_t)r0 * g.N + c0];
                    if (c1ok) v01 += a1p[(size_t)r0 * g.N + c0 + 1];
                }
                if (r1 < g.M) {
                    if (c0ok) v10 += a1p[(size_t)r1 * g.N + c0];
                    if (c1ok) v11 += a1p[(size_t)r1 * g.N + c0 + 1];
                }
            }
            if (g.relu) {
                v00 = v00 > 0.f ? v00 : 0.f; v01 = v01 > 0.f ? v01 : 0.f;
                v10 = v10 > 0.f ? v10 : 0.f; v11 = v11 > 0.f ? v11 : 0.f;
            }
            if (r0 < g.M) {
                if (c0ok) g.C[(size_t)r0 * g.N + c0]     = v00;
                if (c1ok) g.C[(size_t)r0 * g.N + c0 + 1] = v01;
            }
            if (r1 < g.M) {
                if (c0ok) g.C[(size_t)r1 * g.N + c0]     = v10;
                if (c1ok) g.C[(size_t)r1 * g.N + c0 + 1] = v11;
            }
        }
    }
}

// ---------------- host ----------------
static inline int cdiv(int a, int b) { return (a + b - 1) / b; }

static void launch_gemm(cudaStream_t st, int M, int N, int nparts,
                        const float* A0, const float* W0,
                        const float* A1, const float* W1,
                        int nadd, const float* add0, const float* add1,
                        const float* bias, float* C, int relu) {
    GemmArgs g;
    g.A[0] = A0; g.A[1] = A1; g.W[0] = W0; g.W[1] = W1;
    g.add0 = add0; g.add1 = add1;
    g.nparts = nparts; g.nadd = nadd; g.M = M; g.N = N;
    g.bias = bias; g.C = C; g.relu = relu;
    dim3 grid(cdiv(N, 128), cdiv(M, 128));
    gemm_fp16_kernel<<<grid, 256, 0, st>>>(g);
}

extern "C" void kernel_launch(void* const* d_in, const int* in_sizes, int n_in,
                              void* d_out, int out_size) {
    const float* xp = (const float*)d_in[0];
    const float* xa = (const float*)d_in[1];
    const float* xi = (const float*)d_in[2];
    const float* xf = (const float*)d_in[3];
    const int* cites_src = (const int*)d_in[4];
    const int* cites_dst = (const int*)d_in[5];
    const int* writes_src = (const int*)d_in[6];
    const int* writes_dst = (const int*)d_in[7];
    const int* rwrites_src = (const int*)d_in[8];
    const int* rwrites_dst = (const int*)d_in[9];
    const int* raff_src = (const int*)d_in[12];
    const int* raff_dst = (const int*)d_in[13];
    const int* topic_src = (const int*)d_in[14];
    const int* topic_dst = (const int*)d_in[15];
    const int* rtopic_src = (const int*)d_in[16];
    const int* rtopic_dst = (const int*)d_in[17];
    const float* Wl = (const float*)d_in[18];
    const float* bl = (const float*)d_in[19];
    const float* Wr = (const float*)d_in[20];
    const float* Wout = (const float*)d_in[21];
    const float* bout = (const float*)d_in[22];

    // streams/events: created once before graph capture (host resources only)
    static cudaStream_t sMem = 0;
    static cudaEvent_t ev[7];
    if (!sMem) {
        cudaStreamCreateWithFlags(&sMem, cudaStreamNonBlocking);
        for (int i = 0; i < 7; i++)
            cudaEventCreateWithFlags(&ev[i], cudaEventDisableTiming);
    }
    cudaStream_t s0 = 0;  // compute stream (the captured/legacy stream)

    float *m0, *gg1, *gg6, *ma2, *gg4, *mf5, *tA, *tI, *tF;
    float *p1, *p2, *a1, *f1, *WrP, *WrA, *bP, *bA;
    int *cnt_c, *off_c, *adj_c, *cnt_w, *off_w, *adj_w;
    int *cnt_rw, *off_rw, *adj_rw;
    int *cnt_raf, *off_raf, *adj_raf, *cnt_t, *off_t, *adj_t;
    int *cnt_rt, *off_rt, *adj_rt;
    cudaGetSymbolAddress((void**)&m0, g_mp0);
    cudaGetSymbolAddress((void**)&gg1, g_mp1);
    cudaGetSymbolAddress((void**)&gg6, g_mp6);
    cudaGetSymbolAddress((void**)&ma2, g_ma2);
    cudaGetSymbolAddress((void**)&gg4, g_ma4);
    cudaGetSymbolAddress((void**)&mf5, g_mf5);
    cudaGetSymbolAddress((void**)&tA, g_tA);
    cudaGetSymbolAddress((void**)&tI, g_tI);
    cudaGetSymbolAddress((void**)&tF, g_tF);
    cudaGetSymbolAddress((void**)&p1, g_p1);
    cudaGetSymbolAddress((void**)&p2, g_p2);
    cudaGetSymbolAddress((void**)&a1, g_a1);
    cudaGetSymbolAddress((void**)&f1, g_f1);
    cudaGetSymbolAddress((void**)&WrP, g_WrP);
    cudaGetSymbolAddress((void**)&WrA, g_WrA);
    cudaGetSymbolAddress((void**)&bP, g_bP);
    cudaGetSymbolAddress((void**)&bA, g_bA);
    cudaGetSymbolAddress((void**)&cnt_c, g_cnt_c);
    cudaGetSymbolAddress((void**)&off_c, g_off_c);
    cudaGetSymbolAddress((void**)&adj_c, g_adj_c);
    cudaGetSymbolAddress((void**)&cnt_w, g_cnt_w);
    cudaGetSymbolAddress((void**)&off_w, g_off_w);
    cudaGetSymbolAddress((void**)&adj_w, g_adj_w);
    cudaGetSymbolAddress((void**)&cnt_rw, g_cnt_rw);
    cudaGetSymbolAddress((void**)&off_rw, g_off_rw);
    cudaGetSymbolAddress((void**)&adj_rw, g_adj_rw);
    cudaGetSymbolAddress((void**)&cnt_raf, g_cnt_raf);
    cudaGetSymbolAddress((void**)&off_raf, g_off_raf);
    cudaGetSymbolAddress((void**)&adj_raf, g_adj_raf);
    cudaGetSymbolAddress((void**)&cnt_t, g_cnt_t);
    cudaGetSymbolAddress((void**)&off_t, g_off_t);
    cudaGetSymbolAddress((void**)&adj_t, g_adj_t);
    cudaGetSymbolAddress((void**)&cnt_rt, g_cnt_rt);
    cudaGetSymbolAddress((void**)&off_rt, g_off_rt);
    cudaGetSymbolAddress((void**)&adj_rt, g_adj_rt);

    const size_t WSZ = (size_t)HD * HD;
    const float* Wl0 = Wl;                     const float* bl0 = bl;
    const float* Wl1 = Wl + 7 * WSZ;

    // ---- fork memory stream off the capture stream ----
    cudaEventRecord(ev[0], s0);
    cudaStreamWaitEvent(sMem, ev[0], 0);

    // ---- memory stream: CSR builds for the 6 live relations ----
    struct Rel { const int* src; const int* dst; int E; int n_dst; int* cnt; int* off; int* adj; };
    Rel rels[6] = {
        { cites_src,   cites_dst,   E_C, NP, cnt_c,   off_c,   adj_c   },
        { writes_src,  writes_dst,  E_W, NP, cnt_w,   off_w,   adj_w   },
        { rtopic_src,  rtopic_dst,  E_T, NP, cnt_rt,  off_rt,  adj_rt  },
        { rwrites_src, rwrites_dst, E_W, NA, cnt_rw,  off_rw,  adj_rw  },
        { raff_src,    raff_dst,    E_A, NA, cnt_raf, off_raf, adj_raf },
        { topic_src,   topic_dst,   E_T, NF, cnt_t,   off_t,   adj_t   },
    };
    for (int r = 0; r < 6; r++) {
        cudaMemsetAsync(rels[r].cnt, 0, (size_t)rels[r].n_dst * sizeof(int), sMem);
        hist_kernel<<<cdiv(rels[r].E, 256), 256, 0, sMem>>>(rels[r].dst, rels[r].E, rels[r].cnt);
        scan_kernel<<<1, 1024, 0, sMem>>>(rels[r].cnt, rels[r].n_dst, rels[r].off);
        fill_kernel<<<cdiv(rels[r].E, 256), 256, 0, sMem>>>(rels[r].src, rels[r].dst, rels[r].E,
                                                            rels[r].cnt, rels[r].adj);
    }

    // ---- compute stream: combine + L1 src-side transforms (concurrent w/ CSR) ----
    combine_kernel<<<cdiv(2 * HD * HD, 256), 256, 0, s0>>>(Wr, bl, WrP, WrA, bP, bA);
    launch_gemm(s0, NA, HD, 1, xa, Wl0 + 1 * WSZ, 0, 0, 0, 0, 0, 0, tA, 0);
    launch_gemm(s0, NF, HD, 1, xf, Wl0 + 6 * WSZ, 0, 0, 0, 0, 0, 0, tF, 0);
    launch_gemm(s0, NI, HD, 1, xi, Wl0 + 4 * WSZ, 0, 0, 0, 0, 0, 0, tI, 0);
    cudaEventRecord(ev[1], s0);                 // transforms done

    // ---- memory stream: L1 gathers ----
    gather_mean_kernel<<<cdiv(NP, 4), 256, 0, sMem>>>(xp, off_c, adj_c, m0, NP);
    cudaStreamWaitEvent(sMem, ev[1], 0);        // tA/tF/tI ready
    gather_mean_kernel<<<cdiv(NP, 4), 256, 0, sMem>>>(tA, off_w,  adj_w,  gg1, NP);
    gather_mean_kernel<<<cdiv(NP, 4), 256, 0, sMem>>>(tF, off_rt, adj_rt, gg6, NP);
    cudaEventRecord(ev[2], sMem);               // p1's gather inputs ready
    gather_mean_kernel<<<cdiv(NA, 4), 256, 0, sMem>>>(xp, off_rw,  adj_rw,  ma2, NA);
    gather_mean_kernel<<<cdiv(NA, 4), 256, 0, sMem>>>(tI, off_raf, adj_raf, gg4, NA);
    gather_mean_kernel<<<cdiv(NF, 4), 256, 0, sMem>>>(xp, off_t,   adj_t,   mf5, NF);
    cudaEventRecord(ev[3], sMem);               // a1/f1 gather inputs ready

    // ---- compute: p1 (overlaps ma2/gg4/mf5 gathers on sMem) ----
    cudaStreamWaitEvent(s0, ev[2], 0);
    launch_gemm(s0, NP, HD, 2, m0, Wl0 + 0 * WSZ, xp, WrP, 2, gg1, gg6, bP, p1, 1);
    cudaEventRecord(ev[4], s0);                 // p1 done (also: m0/gg1/gg6 free)

    // ---- memory: L2 cites gather on p1 (overlaps a1/f1/tA2/tF2 on s0) ----
    cudaStreamWaitEvent(sMem, ev[4], 0);
    gather_mean_kernel<<<cdiv(NP, 4), 256, 0, sMem>>>(p1, off_c, adj_c, m0, NP);

    // ---- compute: a1, tA2, f1, tF2 ----
    cudaStreamWaitEvent(s0, ev[3], 0);
    launch_gemm(s0, NA, HD, 2, ma2, Wl0 + 2 * WSZ, xa, WrA, 1, gg4, 0, bA, a1, 1);
    launch_gemm(s0, NA, HD, 1, a1, Wl1 + 1 * WSZ, 0, 0, 0, 0, 0, 0, tA, 0);
    cudaEventRecord(ev[5], s0);                 // tA2 ready
    launch_gemm(s0, NF, HD, 2, mf5, Wl0 + 5 * WSZ, xf, Wr + 5 * WSZ,
                0, 0, 0, bl0 + 5 * HD, f1, 1);
    launch_gemm(s0, NF, HD, 1, f1, Wl1 + 6 * WSZ, 0, 0, 0, 0, 0, 0, tF, 0);
    cudaEventRecord(ev[6], s0);                 // tF2 ready

    // ---- memory: L2 writes/rev_topic gathers ----
    cudaStreamWaitEvent(sMem, ev[5], 0);
    gather_mean_kernel<<<cdiv(NP, 4), 256, 0, sMem>>>(tA, off_w,  adj_w,  gg1, NP);
    cudaStreamWaitEvent(sMem, ev[6], 0);
    gather_mean_kernel<<<cdiv(NP, 4), 256, 0, sMem>>>(tF, off_rt, adj_rt, gg6, NP);
    cudaEventRecord(ev[0], sMem);               // all L2 gathers done (join)

    // ---- compute: p2 + output projection (rejoined: sMem fully merged) ----
    cudaStreamWaitEvent(s0, ev[0], 0);
    launch_gemm(s0, NP, HD, 2, m0, Wl1 + 0 * WSZ, p1, WrP + WSZ,
                2, gg1, gg6, bP + HD, p2, 1);
    launch_gemm(s0, NP, NOUT, 1, p2, Wout, 0, 0, 0, 0, 0, bout, (float*)d_out, 0);
}